// round 15
// baseline (speedup 1.0000x reference)
#include <cuda_runtime.h>
#include <cstdint>
#include <math.h>

#define NEG_INF (__int_as_float(0xff800000))

// ---------------- problem constants ----------------
#define BATCH   16
#define NFEAT   16
#define TLEN    64
#define SCL     32
#define HID     128
#define FS      4
#define NHEAD   2
#define DHEAD   64

#define H1H     61
#define H1W     29
#define H2H     58
#define H2W     26
#define LSEQ    1508
#define UTOP    40

#define K1      256
#define K2      2048
#define M1      (BATCH*H1H*H1W)   // 28304
#define M2      (BATCH*LSEQ)      // 24128
#define BHCNT   (BATCH*NHEAD)     // 32

#if defined(__CUDA_ARCH_FEAT_SM103_ALL) || defined(__CUDA_ARCH_SPECIFIC__)
#define TC_PATH 1
#else
#define TC_PATH 0
#endif

// ---------------- scratch ----------------
__device__ float g_xcl[BATCH*TLEN*SCL*NFEAT];
__device__ float g_h1cl[M1*HID];
__device__ float g_part[2*M2*HID];
__device__ float g_Q[BHCNT*LSEQ*DHEAD];
__device__ float g_K[BHCNT*LSEQ*DHEAD];
__device__ float g_V[BHCNT*LSEQ*DHEAD];
__device__ float g_M[BHCNT*LSEQ];
__device__ int   g_Mtop[BHCNT*UTOP];
__device__ float g_upd[BHCNT*UTOP*DHEAD];
__device__ float g_vmean[BHCNT*DHEAD];
__device__ float g_B1[HID*K1];
__device__ float g_B2[HID*K2];
__device__ float g_wqkvT[3*HID*HID];
__device__ float g_woT[HID*HID];
__device__ int   g_sel[BHCNT*LSEQ];

// ---------------- PTX helpers ----------------
__device__ __forceinline__ uint32_t smem_u32(const void* p) {
    uint32_t a;
    asm("{ .reg .u64 t; cvta.to.shared.u64 t, %1; cvt.u32.u64 %0, t; }" : "=r"(a) : "l"(p));
    return a;
}

#define TC_ALLOC(sa, n) \
    asm volatile("tcgen05.alloc.cta_group::1.sync.aligned.shared::cta.b32 [%0], %1;" \
                 :: "r"(sa), "r"(n) : "memory")
#define TC_DEALLOC(t, n) \
    asm volatile("tcgen05.dealloc.cta_group::1.sync.aligned.b32 %0, %1;" :: "r"(t), "r"(n))
#define TC_RELINQ() \
    asm volatile("tcgen05.relinquish_alloc_permit.cta_group::1.sync.aligned;")
#define TC_COMMIT(mb) \
    asm volatile("tcgen05.commit.cta_group::1.mbarrier::arrive::one.shared::cluster.b64 [%0];" \
                 :: "r"(mb) : "memory")
#define TC_FENCE_AFTER()  asm volatile("tcgen05.fence::after_thread_sync;" ::: "memory")
#define TC_FENCE_BEFORE() asm volatile("tcgen05.fence::before_thread_sync;" ::: "memory")
#define TC_WAIT_LD()      asm volatile("tcgen05.wait::ld.sync.aligned;" ::: "memory")
#define MB_INIT(mb, c) \
    asm volatile("mbarrier.init.shared.b64 [%0], %1;" :: "r"(mb), "r"(c) : "memory")
#define FENCE_ASYNC() asm volatile("fence.proxy.async.shared::cta;" ::: "memory")

#define MB_WAIT_PARITY(mbar_smem_addr, phase_parity) do { \
    uint32_t _mbar = (uint32_t)(mbar_smem_addr); \
    uint32_t _parity = (uint32_t)(phase_parity); \
    uint32_t _done; \
    asm volatile( \
        "{\n\t" \
        ".reg .pred p;\n\t" \
        "mbarrier.try_wait.parity.acquire.cta.shared::cta.b64 p, [%1], %2;\n\t" \
        "selp.b32 %0, 1, 0, p;\n\t" \
        "}" \
        : "=r"(_done) : "r"(_mbar), "r"(_parity) : "memory"); \
    if (!_done) { \
        asm volatile( \
            "{\n\t" \
            ".reg .pred P1;\n\t" \
            "WAIT_LOOP_%=:\n\t" \
            "mbarrier.try_wait.parity.acquire.cta.shared::cta.b64 P1, [%0], %1, 0x989680;\n\t" \
            "@P1 bra.uni WAIT_DONE_%=;\n\t" \
            "bra.uni WAIT_LOOP_%=;\n\t" \
            "WAIT_DONE_%=:\n\t" \
            "}" \
            :: "r"(_mbar), "r"(_parity) : "memory"); \
    } \
} while(0)

#define TC_LD_X32(r, tmem_addr) \
    asm volatile( \
        "tcgen05.ld.sync.aligned.32x32b.x32.b32 " \
        "{%0, %1, %2, %3, %4, %5, %6, %7, " \
        " %8, %9, %10, %11, %12, %13, %14, %15, " \
        " %16, %17, %18, %19, %20, %21, %22, %23, " \
        " %24, %25, %26, %27, %28, %29, %30, %31}, [%32];" \
        : "=r"((r)[0]),  "=r"((r)[1]),  "=r"((r)[2]),  "=r"((r)[3]), \
          "=r"((r)[4]),  "=r"((r)[5]),  "=r"((r)[6]),  "=r"((r)[7]), \
          "=r"((r)[8]),  "=r"((r)[9]),  "=r"((r)[10]), "=r"((r)[11]), \
          "=r"((r)[12]), "=r"((r)[13]), "=r"((r)[14]), "=r"((r)[15]), \
          "=r"((r)[16]), "=r"((r)[17]), "=r"((r)[18]), "=r"((r)[19]), \
          "=r"((r)[20]), "=r"((r)[21]), "=r"((r)[22]), "=r"((r)[23]), \
          "=r"((r)[24]), "=r"((r)[25]), "=r"((r)[26]), "=r"((r)[27]), \
          "=r"((r)[28]), "=r"((r)[29]), "=r"((r)[30]), "=r"((r)[31]) \
        : "r"(tmem_addr))

#if TC_PATH
__device__ __forceinline__ void mma_tf32_ss(uint32_t d_tmem, uint64_t a_desc,
                                            uint64_t b_desc, uint32_t idesc, bool accum) {
    uint32_t en = accum ? 1u : 0u;
    asm volatile(
        "{\n\t"
        ".reg .pred p;\n\t"
        "setp.ne.u32 p, %4, 0;\n\t"
        "tcgen05.mma.cta_group::1.kind::tf32 [%0], %1, %2, %3, p;\n\t"
        "}"
        :: "r"(d_tmem), "l"(a_desc), "l"(b_desc), "r"(idesc), "r"(en)
        : "memory");
}
#endif

__device__ __forceinline__ uint64_t make_desc(uint32_t addr) {
    return ((uint64_t)2 << 61) | ((uint64_t)1 << 46) | ((uint64_t)64 << 32)
         | ((uint64_t)1 << 16) | (uint64_t)((addr >> 4) & 0x3FFF);
}

__device__ __forceinline__ uint32_t swz128(uint32_t off) {
    return off ^ ((off >> 3) & 0x70);
}

__device__ __forceinline__ void split_tf32(float v, float& hi, float& lo) {
    uint32_t h;
    asm("cvt.rna.tf32.f32 %0, %1;" : "=r"(h) : "f"(v));
    hi = __uint_as_float(h);
    lo = v - hi;
}

#define TF32_IDESC ((1u << 4) | (2u << 7) | (2u << 10) | (16u << 17) | (8u << 24))

// ---------------- fused prep kernel ----------------
#define PREP_S0 (BATCH*NFEAT*TLEN*SCL)
#define PREP_S1 (PREP_S0 + HID*K1)
#define PREP_S2 (PREP_S1 + HID*K2)
#define PREP_S3 (PREP_S2 + 3*HID*HID)
#define PREP_S4 (PREP_S3 + HID*HID)
__global__ void prep_kernel(const float* __restrict__ x,
                            const float* __restrict__ c1w, const float* __restrict__ c2w,
                            const float* __restrict__ wq, const float* __restrict__ wk,
                            const float* __restrict__ wv, const float* __restrict__ wo,
                            float* __restrict__ xcl, float* __restrict__ B1,
                            float* __restrict__ B2, float* __restrict__ wqkvT,
                            float* __restrict__ woT) {
    int idx = blockIdx.x * blockDim.x + threadIdx.x;
    if (idx < PREP_S0) {
        int w = idx % SCL;
        int h = (idx / SCL) % TLEN;
        int c = (idx / (SCL * TLEN)) % NFEAT;
        int b = idx / (SCL * TLEN * NFEAT);
        xcl[((b * TLEN + h) * SCL + w) * NFEAT + c] = x[idx];
    } else if (idx < PREP_S1) {
        int i = idx - PREP_S0;
        int n = i / K1, k = i % K1;
        int ic = k / 16, s = k % 16;
        B1[n * K1 + s * NFEAT + ic] = c1w[i];
    } else if (idx < PREP_S2) {
        int i = idx - PREP_S1;
        int n = i / K2, k = i % K2;
        int ic = k / 16, s = k % 16;
        B2[n * K2 + s * HID + ic] = c2w[i];
    } else if (idx < PREP_S3) {
        int i = idx - PREP_S2;
        int mat = i / (HID * HID);
        int r = i % (HID * HID);
        int a = r / HID, b = r % HID;
        const float* w = (mat == 0) ? wq : (mat == 1) ? wk : wv;
        wqkvT[mat * HID * HID + b * HID + a] = w[r];
    } else if (idx < PREP_S4) {
        int i = idx - PREP_S3;
        int a = i / HID, b = i % HID;
        woT[b * HID + a] = wo[i];
    }
}

// ---------------- tcgen05 3xTF32 GEMM ----------------
// MODE 0: A row-major. MODE 1: conv1 im2col. MODE 2: conv2 im2col.
// MODE 3: A gathered from (upd|vmean) via sel. MODE 4: A = relu(part0+part1+biasA).
// SPLITK > 1: grid.z splits K; raw partial written to o0 + z*M*HID.
#define GEMM_SMEM_BYTES (79872)

template<int MODE, int KDIM, bool RELU, int NMAT, int LAYOUT, int SPLITK>
__global__ void __launch_bounds__(256, 2)
gemm_tc_kernel(const float* __restrict__ Ain, const float* __restrict__ BwAll,
               const float* __restrict__ b0, const float* __restrict__ b1p,
               const float* __restrict__ b2p,
               float* __restrict__ o0, float* __restrict__ o1p, float* __restrict__ o2p,
               int M,
               const int* __restrict__ sel, const float* __restrict__ updp,
               const float* __restrict__ vmeanp) {
    const int mat = (NMAT > 1) ? blockIdx.y : 0;
    const float* Bw = BwAll + (size_t)mat * HID * KDIM;
    const float* bias = (mat == 0) ? b0 : (mat == 1) ? b1p : b2p;
    float* out = (mat == 0) ? o0 : (mat == 1) ? o1p : o2p;
    const int kbeg = (SPLITK > 1) ? blockIdx.z * (KDIM / SPLITK) : 0;

#if TC_PATH
    extern __shared__ char dynraw[];
    __shared__ uint32_t s_tmem[1];
    __shared__ __align__(8) unsigned long long s_mbar[1];

    const int tid = threadIdx.x;
    const int wid = tid >> 5;
    const int lane = tid & 31;
    const int block_m = blockIdx.x * 128;

    uint32_t dynb32 = smem_u32(dynraw);
    uint32_t smem_base = (dynb32 + 1023u) & ~1023u;
    char* dbase = dynraw + (smem_base - dynb32);
    uint32_t mbar0 = smem_u32(&s_mbar[0]);

    if (wid == 0) {
        TC_ALLOC(smem_u32(s_tmem), 256);
        TC_RELINQ();
    }
    if (tid == 0) MB_INIT(mbar0, 1);
    __syncthreads();
    uint32_t tmem;
    asm volatile("ld.shared.b32 %0, [%1];" : "=r"(tmem) : "r"(smem_u32(s_tmem)));

    const int quad = tid & 7;
    int rowi[4], abase[4], bh2[4];
    bool aok[4];
#pragma unroll
    for (int i = 0; i < 4; i++) {
        rowi[i] = i * 32 + (tid >> 3);
        int m = block_m + rowi[i];
        aok[i] = (m < M);
        int mc = aok[i] ? m : 0;
        bh2[i] = 0;
        if (MODE == 0 || MODE == 4) {
            abase[i] = mc * KDIM;
        } else if (MODE == 1) {
            int b = mc / (H1H * H1W);
            int r = mc % (H1H * H1W);
            abase[i] = ((b * TLEN + r / H1W) * SCL + (r % H1W)) * NFEAT;
        } else if (MODE == 2) {
            int b = mc / LSEQ;
            int r = mc % LSEQ;
            abase[i] = ((b * H1H + r / H2W) * H1W + (r % H2W)) * HID;
        } else {
            int b = mc / LSEQ;
            int l = mc % LSEQ;
            abase[i] = b * NHEAD * LSEQ + l;
            bh2[i] = b * NHEAD;
        }
    }
    uint32_t swz[4];
#pragma unroll
    for (int i = 0; i < 4; i++)
        swz[i] = swz128((uint32_t)rowi[i] * 128u + (uint32_t)quad * 16u);

    float4 areg[4], breg[4];
    auto load_regs = [&](int c) {
        const int kq = kbeg + c * 32 + quad * 4;
#pragma unroll
        for (int i = 0; i < 4; i++) {
            areg[i] = make_float4(0.f, 0.f, 0.f, 0.f);
            if (aok[i]) {
                if (MODE == 3) {
                    int h = kq >> 6, d = kq & 63;
                    int u = __ldg(&sel[abase[i] + h * LSEQ]);
                    int bh = bh2[i] + h;
                    const float* src = (u >= 0)
                        ? updp + ((size_t)bh * UTOP + u) * DHEAD + d
                        : vmeanp + bh * DHEAD + d;
                    areg[i] = *reinterpret_cast<const float4*>(src);
                } else if (MODE == 4) {
                    int addr = abase[i] + kq;
                    float4 p0 = *reinterpret_cast<const float4*>(Ain + addr);
                    float4 p1 = *reinterpret_cast<const float4*>(Ain + (size_t)M2 * HID + addr);
                    float4 bb = *reinterpret_cast<const float4*>(vmeanp + kq);
                    areg[i].x = fmaxf(p0.x + p1.x + bb.x, 0.f);
                    areg[i].y = fmaxf(p0.y + p1.y + bb.y, 0.f);
                    areg[i].z = fmaxf(p0.z + p1.z + bb.z, 0.f);
                    areg[i].w = fmaxf(p0.w + p1.w + bb.w, 0.f);
                } else {
                    int addr;
                    if (MODE == 0) {
                        addr = abase[i] + kq;
                    } else if (MODE == 1) {
                        int s = kq >> 4, ic = kq & 15;
                        addr = abase[i] + (((s >> 2) * SCL) + (s & 3)) * NFEAT + ic;
                    } else {
                        int s = kq >> 7, ic = kq & 127;
                        addr = abase[i] + (((s >> 2) * H1W) + (s & 3)) * HID + ic;
                    }
                    areg[i] = *reinterpret_cast<const float4*>(Ain + addr);
                }
            }
            breg[i] = *reinterpret_cast<const float4*>(Bw + rowi[i] * KDIM + kq);
        }
    };
    auto store_tiles = [&]() {
        char* Ahi = dbase;
        char* Alo = Ahi + 16384;
        char* Bhi = Ahi + 32768;
        char* Blo = Ahi + 49152;
#pragma unroll
        for (int i = 0; i < 4; i++) {
            float4 h4, l4;
            split_tf32(areg[i].x, h4.x, l4.x);
            split_tf32(areg[i].y, h4.y, l4.y);
            split_tf32(areg[i].z, h4.z, l4.z);
            split_tf32(areg[i].w, h4.w, l4.w);
            *reinterpret_cast<float4*>(Ahi + swz[i]) = h4;
            *reinterpret_cast<float4*>(Alo + swz[i]) = l4;
            split_tf32(breg[i].x, h4.x, l4.x);
            split_tf32(breg[i].y, h4.y, l4.y);
            split_tf32(breg[i].z, h4.z, l4.z);
            split_tf32(breg[i].w, h4.w, l4.w);
            *reinterpret_cast<float4*>(Bhi + swz[i]) = h4;
            *reinterpret_cast<float4*>(Blo + swz[i]) = l4;
        }
    };

    const int NC = (KDIM / SPLITK) / 32;
    int ph = 0;
    load_regs(0);

    for (int c = 0; c < NC; c++) {
        if (c > 0) {
            MB_WAIT_PARITY(mbar0, ph);
            ph ^= 1;
        }
        store_tiles();
        if (c + 1 < NC) load_regs(c + 1);
        FENCE_ASYNC();
        __syncthreads();
        if (tid == 0) {
            uint64_t dah = make_desc(smem_base);
            uint64_t dal = make_desc(smem_base + 16384);
            uint64_t dbh = make_desc(smem_base + 32768);
            uint64_t dbl = make_desc(smem_base + 49152);
#pragma unroll
            for (int s = 0; s < 4; s++) {
                uint64_t o = (uint64_t)(s * 2);
                mma_tf32_ss(tmem, dah + o, dbh + o, TF32_IDESC, !(c == 0 && s == 0));
                mma_tf32_ss(tmem, dah + o, dbl + o, TF32_IDESC, true);
                mma_tf32_ss(tmem, dal + o, dbh + o, TF32_IDESC, true);
            }
            TC_COMMIT(mbar0);
        }
    }
    MB_WAIT_PARITY(mbar0, ph);
    TC_FENCE_AFTER();
    __syncthreads();

    if (wid < 4) {
        int m = block_m + wid * 32 + lane;
#pragma unroll
        for (int cb = 0; cb < 128; cb += 32) {
            uint32_t r[32];
            TC_LD_X32(r, tmem + cb);
            TC_WAIT_LD();
            if (m < M) {
                float vals[32];
#pragma unroll
                for (int j = 0; j < 32; j++) {
                    float v = __uint_as_float(r[j]);
                    if (SPLITK == 1) {
                        v += __ldg(&bias[cb + j]);
                        if (RELU) v = fmaxf(v, 0.f);
                    }
                    vals[j] = v;
                }
                float* po;
                if (SPLITK > 1) {
                    po = o0 + ((size_t)blockIdx.z * M + m) * HID + cb;
                } else if (LAYOUT == 0) {
                    po = out + (size_t)m * HID + cb;
                } else {
                    int b = m / LSEQ, l = m % LSEQ;
                    int h = cb >> 6, d0 = cb & 63;
                    po = out + ((size_t)(b * NHEAD + h) * LSEQ + l) * DHEAD + d0;
                }
#pragma unroll
                for (int j = 0; j < 8; j++) {
                    *reinterpret_cast<float4*>(po + j * 4) =
                        make_float4(vals[j * 4], vals[j * 4 + 1], vals[j * 4 + 2], vals[j * 4 + 3]);
                }
            }
        }
        TC_FENCE_BEFORE();
    }
    __syncthreads();
    if (wid == 0) TC_DEALLOC(tmem, 256);
#else
    // naive fallback (family PTX pass; exact sm_103a cubin preferred on GB300)
    const int tid = threadIdx.x;
    const int block_m = blockIdx.x * 128;
    const int kdiv = KDIM / SPLITK;
    for (int e = tid; e < 128 * 128; e += 256) {
        int mi = e >> 7, n = e & 127;
        int m = block_m + mi;
        if (m >= M) continue;
        float acc = 0.f;
        for (int kk = 0; kk < kdiv; kk++) {
            int k = kbeg + kk;
            float a;
            if (MODE == 0) {
                a = Ain[(size_t)m * KDIM + k];
            } else if (MODE == 1) {
                int b = m / (H1H * H1W), r = m % (H1H * H1W);
                int s = k >> 4, ic = k & 15;
                a = Ain[((b * TLEN + r / H1W + (s >> 2)) * SCL + (r % H1W) + (s & 3)) * NFEAT + ic];
            } else if (MODE == 2) {
                int b = m / LSEQ, r = m % LSEQ;
                int s = k >> 7, ic = k & 127;
                a = Ain[((b * H1H + r / H2W + (s >> 2)) * H1W + (r % H2W) + (s & 3)) * HID + ic];
            } else if (MODE == 4) {
                int addr = m * KDIM + k;
                a = fmaxf(Ain[addr] + Ain[(size_t)M2 * HID + addr] + vmeanp[k], 0.f);
            } else {
                int b = m / LSEQ, l = m % LSEQ;
                int h = k >> 6, d = k & 63;
                int u = sel[(b * NHEAD + h) * LSEQ + l];
                int bh = b * NHEAD + h;
                a = (u >= 0) ? updp[((size_t)bh * UTOP + u) * DHEAD + d]
                             : vmeanp[bh * DHEAD + d];
            }
            acc += a * Bw[n * KDIM + k];
        }
        if (SPLITK > 1) {
            o0[((size_t)blockIdx.z * M + m) * HID + n] = acc;
        } else {
            acc += bias[n];
            if (RELU) acc = fmaxf(acc, 0.f);
            if (LAYOUT == 0) {
                out[(size_t)m * HID + n] = acc;
            } else {
                int b = m / LSEQ, l = m % LSEQ;
                int h = n >> 6, d = n & 63;
                out[((size_t)(b * NHEAD + h) * LSEQ + l) * DHEAD + d] = acc;
            }
        }
    }
#endif
}

// ---------------- helpers ----------------
__device__ __forceinline__ float warp_sum(float v) {
    v += __shfl_xor_sync(0xffffffffu, v, 16);
    v += __shfl_xor_sync(0xffffffffu, v, 8);
    v += __shfl_xor_sync(0xffffffffu, v, 4);
    v += __shfl_xor_sync(0xffffffffu, v, 2);
    v += __shfl_xor_sync(0xffffffffu, v, 1);
    return v;
}
__device__ __forceinline__ float warp_max(float v) {
    v = fmaxf(v, __shfl_xor_sync(0xffffffffu, v, 16));
    v = fmaxf(v, __shfl_xor_sync(0xffffffffu, v, 8));
    v = fmaxf(v, __shfl_xor_sync(0xffffffffu, v, 4));
    v = fmaxf(v, __shfl_xor_sync(0xffffffffu, v, 2));
    v = fmaxf(v, __shfl_xor_sync(0xffffffffu, v, 1));
    return v;
}

// ---------------- chunked sampled scores -> M ----------------
// block = (bh, 189-query slice); K streamed through smem in 256-row chunks;
// slice's index rows cached in smem. Warp-uniform membership test per sample.
#define SM_SLICES 8
#define SM_LPS 189
#define SM_CHUNK 256
#define SM_NCHUNK 6
#define SM_SMEM_BYTES (SM_CHUNK*DHEAD*4 + SM_LPS*UTOP*4 + SM_LPS*8 + 256)

__global__ void __launch_bounds__(256, 2)
sampled_m_kernel(const float* __restrict__ Q, const float* __restrict__ K,
                 const int* __restrict__ idxs, float* __restrict__ Mout) {
    extern __shared__ char sm_raw[];
    float* Ks = reinterpret_cast<float*>(sm_raw);                        // 256*64
    int* idx_s = reinterpret_cast<int*>(sm_raw + SM_CHUNK * DHEAD * 4);  // 189*40
    float* ms = reinterpret_cast<float*>(sm_raw + SM_CHUNK * DHEAD * 4 + SM_LPS * UTOP * 4);
    float* ss = ms + SM_LPS;

    int bh = blockIdx.x / SM_SLICES;
    int slice = blockIdx.x % SM_SLICES;
    int lbeg = slice * SM_LPS;
    int lcnt = LSEQ - lbeg; if (lcnt > SM_LPS) lcnt = SM_LPS;
    int tid = threadIdx.x;
    int w = tid >> 5;
    int lane = tid & 31;

    for (int e = tid; e < lcnt * UTOP; e += 256)
        idx_s[e] = idxs[lbeg * UTOP + e];
    for (int e = tid; e < SM_LPS; e += 256) { ms[e] = NEG_INF; ss[e] = 0.f; }
    __syncthreads();

    const float2* Qb = (const float2*)(Q + (size_t)bh * LSEQ * DHEAD);
    const float* Kb = K + (size_t)bh * LSEQ * DHEAD;

    for (int c = 0; c < SM_NCHUNK; c++) {
        int kbase = c * SM_CHUNK;
        int nk = LSEQ - kbase; if (nk > SM_CHUNK) nk = SM_CHUNK;
        for (int e = tid; e < nk * (DHEAD / 4); e += 256) {
            *reinterpret_cast<float4*>(Ks + e * 4) =
                *reinterpret_cast<const float4*>(Kb + (size_t)kbase * DHEAD + e * 4);
        }
        __syncthreads();

        for (int j = w; j < lcnt; j += 8) {
            float2 q = Qb[(size_t)(lbeg + j) * 32 + lane];
            float mx = ms[j], sm = ss[j];
            bool touched = false;
#pragma unroll 1
            for (int u = 0; u < UTOP; u++) {
                int ki = idx_s[j * UTOP + u];
                int r = ki - kbase;
                if ((unsigned)r < (unsigned)nk) {
                    float2 kk = *reinterpret_cast<const float2*>(Ks + r * DHEAD + lane * 2);
                    float d = warp_sum(q.x * kk.x + q.y * kk.y);
                    mx = fmaxf(mx, d);
                    sm += d;
                    touched = true;
                }
            }
            if (touched && lane == 0) { ms[j] = mx; ss[j] = sm; }
        }
        __syncthreads();
    }
    for (int j = tid; j < lcnt; j += 256)
        Mout[bh * LSEQ + lbeg + j] = ms[j] - ss[j] / (float)LSEQ;
}

// ---------------- top-40 via bitonic sort of 2048 keys ----------------
#define SORTN 2048
__global__ void __launch_bounds__(256)
topk_kernel(const float* __restrict__ Min, int* __restrict__ Mtop) {
    __shared__ unsigned long long keys[SORTN];
    int bh = blockIdx.x;
    int tid = threadIdx.x;
    for (int j = tid; j < SORTN; j += 256) {
        unsigned long long key;
        if (j < LSEQ) {
            uint32_t b = __float_as_uint(Min[bh * LSEQ + j]);
            uint32_t s = (b & 0x80000000u) ? ~b : (b | 0x80000000u);
            key = ((unsigned long long)(~s) << 32) | (uint32_t)j;
        } else {
            key = 0xFFFFFFFFFFFFFFFFull;
        }
        keys[j] = key;
    }
    __syncthreads();
    for (int k = 2; k <= SORTN; k <<= 1) {
        for (int j = k >> 1; j > 0; j >>= 1) {
#pragma unroll 4
            for (int t = tid; t < SORTN / 2; t += 256) {
                int i = ((t / j) * j * 2) + (t % j);
                int l2 = i + j;
                bool up = ((i & k) == 0);
                unsigned long long a = keys[i], b = keys[l2];
                if ((a > b) == up) { keys[i] = b; keys[l2] = a; }
            }
            __syncthreads();
        }
    }
    if (tid < UTOP)
        Mtop[bh * UTOP + tid] = (int)(keys[tid] & 0xFFFFFFFFull);
}

// ---------------- V mean per (b,h) ----------------
#define VSLICE 377
__global__ void vmean_kernel(const float* __restrict__ V, float* __restrict__ vmean) {
    __shared__ float part[4][DHEAD];
    int bh = blockIdx.x;
    int tid = threadIdx.x;
    int d = tid & 63;
    int sl = tid >> 6;
    const float* Vb = V + (size_t)bh * LSEQ * DHEAD;
    float s = 0.f;
    int beg = sl * VSLICE, end = beg + VSLICE;
    for (int l = beg; l < end; l++) s += Vb[(size_t)l * DHEAD + d];
    part[sl][d] = s;
    __syncthreads();
    if (tid < DHEAD)
        vmean[bh * DHEAD + tid] =
            (part[0][tid] + part[1][tid] + part[2][tid] + part[3][tid]) / (float)LSEQ;
}

// ---------------- attention: tiled multi-query (R14 version, kept) ----------------
#define AQ 8
#define NCHUNK ((LSEQ + 31) / 32)
__global__ void __launch_bounds__(256)
attn_kernel(const float* __restrict__ Q, const float* __restrict__ K,
            const float* __restrict__ V, const int* __restrict__ Mtop,
            float* __restrict__ upd) {
    __shared__ float qs[AQ][DHEAD];
    __shared__ float Ks[32][65];
    __shared__ float2 Vs[32][33];
    __shared__ float ps[AQ][32];
    int bh = blockIdx.x / 5;
    int grp = blockIdx.x % 5;
    int tid = threadIdx.x;
    int w = tid >> 5;
    int lane = tid & 31;
    int u = grp * AQ + w;
    int qi = bh * UTOP + u;

    for (int e = tid; e < AQ * DHEAD; e += 256) {
        int uu = e >> 6, d = e & 63;
        int ll = Mtop[bh * UTOP + grp * AQ + uu];
        qs[uu][d] = Q[((size_t)bh * LSEQ + ll) * DHEAD + d];
    }
    __syncthreads();

    const float* Kb = K + (size_t)bh * LSEQ * DHEAD;
    const float* Vb = V + (size_t)bh * LSEQ * DHEAD;

    float m = NEG_INF, s = 0.f, acc0 = 0.f, acc1 = 0.f;

    for (int c = 0; c < NCHUNK; c++) {
        int base = c * 32;
        int nk = LSEQ - base; if (nk > 32) nk = 32;
        for (int e = tid; e < nk * DHEAD; e += 256) {
            int row = e >> 6, d = e & 63;
            Ks[row][d] = Kb[(size_t)(base + row) * DHEAD + d];
        }
        for (int e = tid; e < nk * 32; e += 256) {
            int row = e >> 5, dp = e & 31;
            Vs[row][dp] = *reinterpret_cast<const float2*>(
                Vb + (size_t)(base + row) * DHEAD + dp * 2);
        }
        __syncthreads();

        bool valid = (lane < nk);
        float dot = 0.f;
#pragma unroll 16
        for (int d = 0; d < DHEAD; d++)
            dot += Ks[lane][d] * qs[w][d];
        dot *= 0.125f;
        if (!valid) dot = NEG_INF;
        float cm = warp_max(dot);
        float nm = fmaxf(m, cm);
        float scale = __expf(m - nm);
        float p = valid ? __expf(dot - nm) : 0.f;
        ps[w][lane] = p;
        float cs = warp_sum(p);
        s = s * scale + cs;
        acc0 *= scale;
        acc1 *= scale;
        m = nm;
        __syncwarp();
#pragma unroll 8
        for (int k = 0; k < 32; k++) {
            float pk = ps[w][k];
            float2 vv = Vs[k][lane];
            acc0 += pk * vv.x;
            acc1 += pk * vv.y;
        }
        __syncthreads();
    }
    float inv = 1.f / s;
    upd[(size_t)qi * DHEAD + lane * 2]     = acc0 * inv;
    upd[(size_t)qi * DHEAD + lane * 2 + 1] = acc1 * inv;
}

// ---------------- sel map ----------------
__global__ void selinit_kernel(int* __restrict__ sel) {
    int idx = blockIdx.x * blockDim.x + threadIdx.x;
    if (idx < BHCNT * LSEQ) sel[idx] = -1;
}
__global__ void selset_kernel(const int* __restrict__ Mtop, int* __restrict__ sel) {
    int idx = blockIdx.x * blockDim.x + threadIdx.x;
    if (idx >= BHCNT * UTOP) return;
    sel[(idx / UTOP) * LSEQ + Mtop[idx]] = idx % UTOP;
}

// ---------------- launch ----------------
extern "C" void kernel_launch(void* const* d_in, const int* in_sizes, int n_in,
                              void* d_out, int out_size) {
    const float* x       = (const float*)d_in[0];
    const float* conv1_w = (const float*)d_in[1];
    const float* conv1_b = (const float*)d_in[2];
    const float* conv2_w = (const float*)d_in[3];
    const float* conv2_b = (const float*)d_in[4];
    const float* wq = (const float*)d_in[5];
    const float* bq = (const float*)d_in[6];
    const float* wk = (const float*)d_in[7];
    const float* bk = (const float*)d_in[8];
    const float* wv = (const float*)d_in[9];
    const float* bv = (const float*)d_in[10];
    const float* wo = (const float*)d_in[11];
    const float* bo = (const float*)d_in[12];
    const int* index_sample = (const int*)d_in[13];
    float* out = (float*)d_out;

    float *xcl, *h1cl, *part, *Qp, *Kp, *Vp, *Mv, *updv, *vmeanv;
    float *B1, *B2, *wqkvT, *woT;
    int *mtop, *sel;
    cudaGetSymbolAddress((void**)&xcl, g_xcl);
    cudaGetSymbolAddress((void**)&h1cl, g_h1cl);
    cudaGetSymbolAddress((void**)&part, g_part);
    cudaGetSymbolAddress((void**)&Qp, g_Q);
    cudaGetSymbolAddress((void**)&Kp, g_K);
    cudaGetSymbolAddress((void**)&Vp, g_V);
    cudaGetSymbolAddress((void**)&Mv, g_M);
    cudaGetSymbolAddress((void**)&mtop, g_Mtop);
    cudaGetSymbolAddress((void**)&updv, g_upd);
    cudaGetSymbolAddress((void**)&vmeanv, g_vmean);
    cudaGetSymbolAddress((void**)&B1, g_B1);
    cudaGetSymbolAddress((void**)&B2, g_B2);
    cudaGetSymbolAddress((void**)&wqkvT, g_wqkvT);
    cudaGetSymbolAddress((void**)&woT, g_woT);
    cudaGetSymbolAddress((void**)&sel, g_sel);

    cudaFuncSetAttribute((const void*)gemm_tc_kernel<1, K1, true, 1, 0, 1>,
                         cudaFuncAttributeMaxDynamicSharedMemorySize, GEMM_SMEM_BYTES);
    cudaFuncSetAttribute((const void*)gemm_tc_kernel<2, K2, false, 1, 0, 2>,
                         cudaFuncAttributeMaxDynamicSharedMemorySize, GEMM_SMEM_BYTES);
    cudaFuncSetAttribute((const void*)gemm_tc_kernel<4, HID, false, 3, 1, 1>,
                         cudaFuncAttributeMaxDynamicSharedMemorySize, GEMM_SMEM_BYTES);
    cudaFuncSetAttribute((const void*)gemm_tc_kernel<3, HID, false, 1, 0, 1>,
                         cudaFuncAttributeMaxDynamicSharedMemorySize, GEMM_SMEM_BYTES);
    cudaFuncSetAttribute((const void*)sampled_m_kernel,
                         cudaFuncAttributeMaxDynamicSharedMemorySize, SM_SMEM_BYTES);

    // fused prep
    prep_kernel<<<(PREP_S4 + 255) / 256, 256>>>(x, conv1_w, conv2_w, wq, wk, wv, wo,
                                                xcl, B1, B2, wqkvT, woT);

    // conv1 -> h1cl (NHWC row-major), relu
    gemm_tc_kernel<1, K1, true, 1, 0, 1>
        <<<(M1 + 127) / 128, 256, GEMM_SMEM_BYTES>>>(xcl, B1, conv1_b, conv1_b, conv1_b,
                                                     h1cl, h1cl, h1cl, M1,
                                                     nullptr, nullptr, nullptr);

    // conv2 split-K=2 -> raw partials
    gemm_tc_kernel<2, K2, false, 1, 0, 2>
        <<<dim3((M2 + 127) / 128, 1, 2), 256, GEMM_SMEM_BYTES>>>(
            h1cl, B2, conv2_b, conv2_b, conv2_b, part, part, part, M2,
            nullptr, nullptr, nullptr);

    // QKV with fused partial-reduce (+conv2 bias, relu) in the A path
    gemm_tc_kernel<4, HID, false, 3, 1, 1>
        <<<dim3((M2 + 127) / 128, 3), 256, GEMM_SMEM_BYTES>>>(part, wqkvT, bq, bk, bv,
                                                              Qp, Kp, Vp, M2,
                                                              nullptr, nullptr, conv2_b);

    // chunked sampled scores -> M
    sampled_m_kernel<<<BHCNT * SM_SLICES, 256, SM_SMEM_BYTES>>>(Qp, Kp, index_sample, Mv);

    // top-40 (bitonic) + vmean
    topk_kernel<<<BHCNT, 256>>>(Mv, mtop);
    vmean_kernel<<<BHCNT, 256>>>(Vp, vmeanv);

    // sel map
    selinit_kernel<<<(BHCNT * LSEQ + 255) / 256, 256>>>(sel);
    selset_kernel<<<(BHCNT * UTOP + 255) / 256, 256>>>(mtop, sel);

    // attention (tiled multi-query)
    attn_kernel<<<BHCNT * 5, 256>>>(Qp, Kp, Vp, mtop, updv);

    // final projection with fused ctx gather (MODE 3)
    gemm_tc_kernel<3, HID, false, 1, 0, 1>
        <<<(M2 + 127) / 128, 256, GEMM_SMEM_BYTES>>>(nullptr, woT, bo, bo, bo,
                                                     out, out, out, M2,
                                                     sel, updv, vmeanv);
}

// round 16
// speedup vs baseline: 1.8696x; 1.8696x over previous
#include <cuda_runtime.h>
#include <cstdint>
#include <math.h>

#define NEG_INF (__int_as_float(0xff800000))

// ---------------- problem constants ----------------
#define BATCH   16
#define NFEAT   16
#define TLEN    64
#define SCL     32
#define HID     128
#define FS      4
#define NHEAD   2
#define DHEAD   64

#define H1H     61
#define H1W     29
#define H2H     58
#define H2W     26
#define LSEQ    1508
#define UTOP    40

#define K1      256
#define K2      2048
#define M1      (BATCH*H1H*H1W)   // 28304
#define M2      (BATCH*LSEQ)      // 24128
#define BHCNT   (BATCH*NHEAD)     // 32

#if defined(__CUDA_ARCH_FEAT_SM103_ALL) || defined(__CUDA_ARCH_SPECIFIC__)
#define TC_PATH 1
#else
#define TC_PATH 0
#endif

// ---------------- scratch ----------------
__device__ float g_xcl[BATCH*TLEN*SCL*NFEAT];
__device__ float g_h1cl[M1*HID];
__device__ float g_part[2*M2*HID];
__device__ float g_Q[BHCNT*LSEQ*DHEAD];
__device__ float g_K[BHCNT*LSEQ*DHEAD];
__device__ float g_V[BHCNT*LSEQ*DHEAD];
__device__ float g_M[BHCNT*LSEQ];
__device__ int   g_Mtop[BHCNT*UTOP];
__device__ float g_upd[BHCNT*UTOP*DHEAD];
__device__ float g_vmean[BHCNT*DHEAD];
__device__ float g_B1[HID*K1];
__device__ float g_B2[HID*K2];
__device__ float g_wqkvT[3*HID*HID];
__device__ float g_woT[HID*HID];
__device__ int   g_sel[BHCNT*LSEQ];

// ---------------- PTX helpers ----------------
__device__ __forceinline__ uint32_t smem_u32(const void* p) {
    uint32_t a;
    asm("{ .reg .u64 t; cvta.to.shared.u64 t, %1; cvt.u32.u64 %0, t; }" : "=r"(a) : "l"(p));
    return a;
}

#define TC_ALLOC(sa, n) \
    asm volatile("tcgen05.alloc.cta_group::1.sync.aligned.shared::cta.b32 [%0], %1;" \
                 :: "r"(sa), "r"(n) : "memory")
#define TC_DEALLOC(t, n) \
    asm volatile("tcgen05.dealloc.cta_group::1.sync.aligned.b32 %0, %1;" :: "r"(t), "r"(n))
#define TC_RELINQ() \
    asm volatile("tcgen05.relinquish_alloc_permit.cta_group::1.sync.aligned;")
#define TC_COMMIT(mb) \
    asm volatile("tcgen05.commit.cta_group::1.mbarrier::arrive::one.shared::cluster.b64 [%0];" \
                 :: "r"(mb) : "memory")
#define TC_FENCE_AFTER()  asm volatile("tcgen05.fence::after_thread_sync;" ::: "memory")
#define TC_FENCE_BEFORE() asm volatile("tcgen05.fence::before_thread_sync;" ::: "memory")
#define TC_WAIT_LD()      asm volatile("tcgen05.wait::ld.sync.aligned;" ::: "memory")
#define MB_INIT(mb, c) \
    asm volatile("mbarrier.init.shared.b64 [%0], %1;" :: "r"(mb), "r"(c) : "memory")
#define FENCE_ASYNC() asm volatile("fence.proxy.async.shared::cta;" ::: "memory")

#define MB_WAIT_PARITY(mbar_smem_addr, phase_parity) do { \
    uint32_t _mbar = (uint32_t)(mbar_smem_addr); \
    uint32_t _parity = (uint32_t)(phase_parity); \
    uint32_t _done; \
    asm volatile( \
        "{\n\t" \
        ".reg .pred p;\n\t" \
        "mbarrier.try_wait.parity.acquire.cta.shared::cta.b64 p, [%1], %2;\n\t" \
        "selp.b32 %0, 1, 0, p;\n\t" \
        "}" \
        : "=r"(_done) : "r"(_mbar), "r"(_parity) : "memory"); \
    if (!_done) { \
        asm volatile( \
            "{\n\t" \
            ".reg .pred P1;\n\t" \
            "WAIT_LOOP_%=:\n\t" \
            "mbarrier.try_wait.parity.acquire.cta.shared::cta.b64 P1, [%0], %1, 0x989680;\n\t" \
            "@P1 bra.uni WAIT_DONE_%=;\n\t" \
            "bra.uni WAIT_LOOP_%=;\n\t" \
            "WAIT_DONE_%=:\n\t" \
            "}" \
            :: "r"(_mbar), "r"(_parity) : "memory"); \
    } \
} while(0)

#define TC_LD_X32(r, tmem_addr) \
    asm volatile( \
        "tcgen05.ld.sync.aligned.32x32b.x32.b32 " \
        "{%0, %1, %2, %3, %4, %5, %6, %7, " \
        " %8, %9, %10, %11, %12, %13, %14, %15, " \
        " %16, %17, %18, %19, %20, %21, %22, %23, " \
        " %24, %25, %26, %27, %28, %29, %30, %31}, [%32];" \
        : "=r"((r)[0]),  "=r"((r)[1]),  "=r"((r)[2]),  "=r"((r)[3]), \
          "=r"((r)[4]),  "=r"((r)[5]),  "=r"((r)[6]),  "=r"((r)[7]), \
          "=r"((r)[8]),  "=r"((r)[9]),  "=r"((r)[10]), "=r"((r)[11]), \
          "=r"((r)[12]), "=r"((r)[13]), "=r"((r)[14]), "=r"((r)[15]), \
          "=r"((r)[16]), "=r"((r)[17]), "=r"((r)[18]), "=r"((r)[19]), \
          "=r"((r)[20]), "=r"((r)[21]), "=r"((r)[22]), "=r"((r)[23]), \
          "=r"((r)[24]), "=r"((r)[25]), "=r"((r)[26]), "=r"((r)[27]), \
          "=r"((r)[28]), "=r"((r)[29]), "=r"((r)[30]), "=r"((r)[31]) \
        : "r"(tmem_addr))

#if TC_PATH
__device__ __forceinline__ void mma_tf32_ss(uint32_t d_tmem, uint64_t a_desc,
                                            uint64_t b_desc, uint32_t idesc, bool accum) {
    uint32_t en = accum ? 1u : 0u;
    asm volatile(
        "{\n\t"
        ".reg .pred p;\n\t"
        "setp.ne.u32 p, %4, 0;\n\t"
        "tcgen05.mma.cta_group::1.kind::tf32 [%0], %1, %2, %3, p;\n\t"
        "}"
        :: "r"(d_tmem), "l"(a_desc), "l"(b_desc), "r"(idesc), "r"(en)
        : "memory");
}
#endif

__device__ __forceinline__ uint64_t make_desc(uint32_t addr) {
    return ((uint64_t)2 << 61) | ((uint64_t)1 << 46) | ((uint64_t)64 << 32)
         | ((uint64_t)1 << 16) | (uint64_t)((addr >> 4) & 0x3FFF);
}

__device__ __forceinline__ uint32_t swz128(uint32_t off) {
    return off ^ ((off >> 3) & 0x70);
}

__device__ __forceinline__ void split_tf32(float v, float& hi, float& lo) {
    uint32_t h;
    asm("cvt.rna.tf32.f32 %0, %1;" : "=r"(h) : "f"(v));
    hi = __uint_as_float(h);
    lo = v - hi;
}

#define TF32_IDESC ((1u << 4) | (2u << 7) | (2u << 10) | (16u << 17) | (8u << 24))

// ---------------- fused prep kernel ----------------
#define PREP_S0 (BATCH*NFEAT*TLEN*SCL)
#define PREP_S1 (PREP_S0 + HID*K1)
#define PREP_S2 (PREP_S1 + HID*K2)
#define PREP_S3 (PREP_S2 + 3*HID*HID)
#define PREP_S4 (PREP_S3 + HID*HID)
__global__ void prep_kernel(const float* __restrict__ x,
                            const float* __restrict__ c1w, const float* __restrict__ c2w,
                            const float* __restrict__ wq, const float* __restrict__ wk,
                            const float* __restrict__ wv, const float* __restrict__ wo,
                            float* __restrict__ xcl, float* __restrict__ B1,
                            float* __restrict__ B2, float* __restrict__ wqkvT,
                            float* __restrict__ woT) {
    int idx = blockIdx.x * blockDim.x + threadIdx.x;
    if (idx < PREP_S0) {
        int w = idx % SCL;
        int h = (idx / SCL) % TLEN;
        int c = (idx / (SCL * TLEN)) % NFEAT;
        int b = idx / (SCL * TLEN * NFEAT);
        xcl[((b * TLEN + h) * SCL + w) * NFEAT + c] = x[idx];
    } else if (idx < PREP_S1) {
        int i = idx - PREP_S0;
        int n = i / K1, k = i % K1;
        int ic = k / 16, s = k % 16;
        B1[n * K1 + s * NFEAT + ic] = c1w[i];
    } else if (idx < PREP_S2) {
        int i = idx - PREP_S1;
        int n = i / K2, k = i % K2;
        int ic = k / 16, s = k % 16;
        B2[n * K2 + s * HID + ic] = c2w[i];
    } else if (idx < PREP_S3) {
        int i = idx - PREP_S2;
        int mat = i / (HID * HID);
        int r = i % (HID * HID);
        int a = r / HID, b = r % HID;
        const float* w = (mat == 0) ? wq : (mat == 1) ? wk : wv;
        wqkvT[mat * HID * HID + b * HID + a] = w[r];
    } else if (idx < PREP_S4) {
        int i = idx - PREP_S3;
        int a = i / HID, b = i % HID;
        woT[b * HID + a] = wo[i];
    }
}

// ---------------- tcgen05 3xTF32 GEMM ----------------
// MODE 0: A row-major. MODE 1: conv1 im2col. MODE 2: conv2 im2col.
// MODE 3: A gathered from (upd|vmean) via sel. MODE 4: A = relu(part0+part1+biasA).
// SPLITK > 1: grid.z splits K; raw partial written to o0 + z*M*HID.
#define GEMM_SMEM_BYTES (79872)

template<int MODE, int KDIM, bool RELU, int NMAT, int LAYOUT, int SPLITK>
__global__ void __launch_bounds__(256, 2)
gemm_tc_kernel(const float* __restrict__ Ain, const float* __restrict__ BwAll,
               const float* __restrict__ b0, const float* __restrict__ b1p,
               const float* __restrict__ b2p,
               float* __restrict__ o0, float* __restrict__ o1p, float* __restrict__ o2p,
               int M,
               const int* __restrict__ sel, const float* __restrict__ updp,
               const float* __restrict__ vmeanp) {
    const int mat = (NMAT > 1) ? blockIdx.y : 0;
    const float* Bw = BwAll + (size_t)mat * HID * KDIM;
    const float* bias = (mat == 0) ? b0 : (mat == 1) ? b1p : b2p;
    float* out = (mat == 0) ? o0 : (mat == 1) ? o1p : o2p;
    const int kbeg = (SPLITK > 1) ? blockIdx.z * (KDIM / SPLITK) : 0;

#if TC_PATH
    extern __shared__ char dynraw[];
    __shared__ uint32_t s_tmem[1];
    __shared__ __align__(8) unsigned long long s_mbar[1];

    const int tid = threadIdx.x;
    const int wid = tid >> 5;
    const int lane = tid & 31;
    const int block_m = blockIdx.x * 128;

    uint32_t dynb32 = smem_u32(dynraw);
    uint32_t smem_base = (dynb32 + 1023u) & ~1023u;
    char* dbase = dynraw + (smem_base - dynb32);
    uint32_t mbar0 = smem_u32(&s_mbar[0]);

    if (wid == 0) {
        TC_ALLOC(smem_u32(s_tmem), 256);
        TC_RELINQ();
    }
    if (tid == 0) MB_INIT(mbar0, 1);
    __syncthreads();
    uint32_t tmem;
    asm volatile("ld.shared.b32 %0, [%1];" : "=r"(tmem) : "r"(smem_u32(s_tmem)));

    const int quad = tid & 7;
    int rowi[4], abase[4], bh2[4];
    bool aok[4];
#pragma unroll
    for (int i = 0; i < 4; i++) {
        rowi[i] = i * 32 + (tid >> 3);
        int m = block_m + rowi[i];
        aok[i] = (m < M);
        int mc = aok[i] ? m : 0;
        bh2[i] = 0;
        if (MODE == 0 || MODE == 4) {
            abase[i] = mc * KDIM;
        } else if (MODE == 1) {
            int b = mc / (H1H * H1W);
            int r = mc % (H1H * H1W);
            abase[i] = ((b * TLEN + r / H1W) * SCL + (r % H1W)) * NFEAT;
        } else if (MODE == 2) {
            int b = mc / LSEQ;
            int r = mc % LSEQ;
            abase[i] = ((b * H1H + r / H2W) * H1W + (r % H2W)) * HID;
        } else {
            int b = mc / LSEQ;
            int l = mc % LSEQ;
            abase[i] = b * NHEAD * LSEQ + l;
            bh2[i] = b * NHEAD;
        }
    }
    uint32_t swz[4];
#pragma unroll
    for (int i = 0; i < 4; i++)
        swz[i] = swz128((uint32_t)rowi[i] * 128u + (uint32_t)quad * 16u);

    float4 areg[4], breg[4];
    auto load_regs = [&](int c) {
        const int kq = kbeg + c * 32 + quad * 4;
#pragma unroll
        for (int i = 0; i < 4; i++) {
            areg[i] = make_float4(0.f, 0.f, 0.f, 0.f);
            if (aok[i]) {
                if (MODE == 3) {
                    int h = kq >> 6, d = kq & 63;
                    int u = __ldg(&sel[abase[i] + h * LSEQ]);
                    int bh = bh2[i] + h;
                    const float* src = (u >= 0)
                        ? updp + ((size_t)bh * UTOP + u) * DHEAD + d
                        : vmeanp + bh * DHEAD + d;
                    areg[i] = *reinterpret_cast<const float4*>(src);
                } else if (MODE == 4) {
                    int addr = abase[i] + kq;
                    float4 p0 = *reinterpret_cast<const float4*>(Ain + addr);
                    float4 p1 = *reinterpret_cast<const float4*>(Ain + (size_t)M2 * HID + addr);
                    float4 bb = *reinterpret_cast<const float4*>(vmeanp + kq);
                    areg[i].x = fmaxf(p0.x + p1.x + bb.x, 0.f);
                    areg[i].y = fmaxf(p0.y + p1.y + bb.y, 0.f);
                    areg[i].z = fmaxf(p0.z + p1.z + bb.z, 0.f);
                    areg[i].w = fmaxf(p0.w + p1.w + bb.w, 0.f);
                } else {
                    int addr;
                    if (MODE == 0) {
                        addr = abase[i] + kq;
                    } else if (MODE == 1) {
                        int s = kq >> 4, ic = kq & 15;
                        addr = abase[i] + (((s >> 2) * SCL) + (s & 3)) * NFEAT + ic;
                    } else {
                        int s = kq >> 7, ic = kq & 127;
                        addr = abase[i] + (((s >> 2) * H1W) + (s & 3)) * HID + ic;
                    }
                    areg[i] = *reinterpret_cast<const float4*>(Ain + addr);
                }
            }
            breg[i] = *reinterpret_cast<const float4*>(Bw + rowi[i] * KDIM + kq);
        }
    };
    auto store_tiles = [&]() {
        char* Ahi = dbase;
        char* Alo = Ahi + 16384;
        char* Bhi = Ahi + 32768;
        char* Blo = Ahi + 49152;
#pragma unroll
        for (int i = 0; i < 4; i++) {
            float4 h4, l4;
            split_tf32(areg[i].x, h4.x, l4.x);
            split_tf32(areg[i].y, h4.y, l4.y);
            split_tf32(areg[i].z, h4.z, l4.z);
            split_tf32(areg[i].w, h4.w, l4.w);
            *reinterpret_cast<float4*>(Ahi + swz[i]) = h4;
            *reinterpret_cast<float4*>(Alo + swz[i]) = l4;
            split_tf32(breg[i].x, h4.x, l4.x);
            split_tf32(breg[i].y, h4.y, l4.y);
            split_tf32(breg[i].z, h4.z, l4.z);
            split_tf32(breg[i].w, h4.w, l4.w);
            *reinterpret_cast<float4*>(Bhi + swz[i]) = h4;
            *reinterpret_cast<float4*>(Blo + swz[i]) = l4;
        }
    };

    const int NC = (KDIM / SPLITK) / 32;
    int ph = 0;
    load_regs(0);

    for (int c = 0; c < NC; c++) {
        if (c > 0) {
            MB_WAIT_PARITY(mbar0, ph);
            ph ^= 1;
        }
        store_tiles();
        if (c + 1 < NC) load_regs(c + 1);
        FENCE_ASYNC();
        __syncthreads();
        if (tid == 0) {
            uint64_t dah = make_desc(smem_base);
            uint64_t dal = make_desc(smem_base + 16384);
            uint64_t dbh = make_desc(smem_base + 32768);
            uint64_t dbl = make_desc(smem_base + 49152);
#pragma unroll
            for (int s = 0; s < 4; s++) {
                uint64_t o = (uint64_t)(s * 2);
                mma_tf32_ss(tmem, dah + o, dbh + o, TF32_IDESC, !(c == 0 && s == 0));
                mma_tf32_ss(tmem, dah + o, dbl + o, TF32_IDESC, true);
                mma_tf32_ss(tmem, dal + o, dbh + o, TF32_IDESC, true);
            }
            TC_COMMIT(mbar0);
        }
    }
    MB_WAIT_PARITY(mbar0, ph);
    TC_FENCE_AFTER();
    __syncthreads();

    if (wid < 4) {
        int m = block_m + wid * 32 + lane;
#pragma unroll
        for (int cb = 0; cb < 128; cb += 32) {
            uint32_t r[32];
            TC_LD_X32(r, tmem + cb);
            TC_WAIT_LD();
            if (m < M) {
                float vals[32];
#pragma unroll
                for (int j = 0; j < 32; j++) {
                    float v = __uint_as_float(r[j]);
                    if (SPLITK == 1) {
                        v += __ldg(&bias[cb + j]);
                        if (RELU) v = fmaxf(v, 0.f);
                    }
                    vals[j] = v;
                }
                float* po;
                if (SPLITK > 1) {
                    po = o0 + ((size_t)blockIdx.z * M + m) * HID + cb;
                } else if (LAYOUT == 0) {
                    po = out + (size_t)m * HID + cb;
                } else {
                    int b = m / LSEQ, l = m % LSEQ;
                    int h = cb >> 6, d0 = cb & 63;
                    po = out + ((size_t)(b * NHEAD + h) * LSEQ + l) * DHEAD + d0;
                }
#pragma unroll
                for (int j = 0; j < 8; j++) {
                    *reinterpret_cast<float4*>(po + j * 4) =
                        make_float4(vals[j * 4], vals[j * 4 + 1], vals[j * 4 + 2], vals[j * 4 + 3]);
                }
            }
        }
        TC_FENCE_BEFORE();
    }
    __syncthreads();
    if (wid == 0) TC_DEALLOC(tmem, 256);
#else
    // naive fallback (family PTX pass; exact sm_103a cubin preferred on GB300)
    const int tid = threadIdx.x;
    const int block_m = blockIdx.x * 128;
    const int kdiv = KDIM / SPLITK;
    for (int e = tid; e < 128 * 128; e += 256) {
        int mi = e >> 7, n = e & 127;
        int m = block_m + mi;
        if (m >= M) continue;
        float acc = 0.f;
        for (int kk = 0; kk < kdiv; kk++) {
            int k = kbeg + kk;
            float a;
            if (MODE == 0) {
                a = Ain[(size_t)m * KDIM + k];
            } else if (MODE == 1) {
                int b = m / (H1H * H1W), r = m % (H1H * H1W);
                int s = k >> 4, ic = k & 15;
                a = Ain[((b * TLEN + r / H1W + (s >> 2)) * SCL + (r % H1W) + (s & 3)) * NFEAT + ic];
            } else if (MODE == 2) {
                int b = m / LSEQ, r = m % LSEQ;
                int s = k >> 7, ic = k & 127;
                a = Ain[((b * H1H + r / H2W + (s >> 2)) * H1W + (r % H2W) + (s & 3)) * HID + ic];
            } else if (MODE == 4) {
                int addr = m * KDIM + k;
                a = fmaxf(Ain[addr] + Ain[(size_t)M2 * HID + addr] + vmeanp[k], 0.f);
            } else {
                int b = m / LSEQ, l = m % LSEQ;
                int h = k >> 6, d = k & 63;
                int u = sel[(b * NHEAD + h) * LSEQ + l];
                int bh = b * NHEAD + h;
                a = (u >= 0) ? updp[((size_t)bh * UTOP + u) * DHEAD + d]
                             : vmeanp[bh * DHEAD + d];
            }
            acc += a * Bw[n * KDIM + k];
        }
        if (SPLITK > 1) {
            o0[((size_t)blockIdx.z * M + m) * HID + n] = acc;
        } else {
            acc += bias[n];
            if (RELU) acc = fmaxf(acc, 0.f);
            if (LAYOUT == 0) {
                out[(size_t)m * HID + n] = acc;
            } else {
                int b = m / LSEQ, l = m % LSEQ;
                int h = n >> 6, d = n & 63;
                out[((size_t)(b * NHEAD + h) * LSEQ + l) * DHEAD + d] = acc;
            }
        }
    }
#endif
}

// ---------------- helpers ----------------
__device__ __forceinline__ float warp_sum(float v) {
    v += __shfl_xor_sync(0xffffffffu, v, 16);
    v += __shfl_xor_sync(0xffffffffu, v, 8);
    v += __shfl_xor_sync(0xffffffffu, v, 4);
    v += __shfl_xor_sync(0xffffffffu, v, 2);
    v += __shfl_xor_sync(0xffffffffu, v, 1);
    return v;
}
__device__ __forceinline__ float warp_max(float v) {
    v = fmaxf(v, __shfl_xor_sync(0xffffffffu, v, 16));
    v = fmaxf(v, __shfl_xor_sync(0xffffffffu, v, 8));
    v = fmaxf(v, __shfl_xor_sync(0xffffffffu, v, 4));
    v = fmaxf(v, __shfl_xor_sync(0xffffffffu, v, 2));
    v = fmaxf(v, __shfl_xor_sync(0xffffffffu, v, 1));
    return v;
}

// ---------------- sampled scores -> M (R14 per-warp version) ----------------
__global__ void sampled_m_kernel(const float* __restrict__ Q, const float* __restrict__ K,
                                 const int* __restrict__ idxs, float* __restrict__ Mout) {
    int gwarp = (blockIdx.x * blockDim.x + threadIdx.x) >> 5;
    int lane = threadIdx.x & 31;
    if (gwarp >= BHCNT * LSEQ) return;
    int bh = gwarp / LSEQ;
    int l  = gwarp % LSEQ;
    const float* q = Q + (size_t)gwarp * DHEAD;
    float q0 = q[lane * 2], q1 = q[lane * 2 + 1];
    const float* Kb = K + (size_t)bh * LSEQ * DHEAD;
    float mx = NEG_INF, sm = 0.f;
#pragma unroll 1
    for (int u = 0; u < UTOP; u += 8) {
        float d[8];
#pragma unroll
        for (int j = 0; j < 8; j++) {
            int ki = __ldg(&idxs[l * UTOP + u + j]);
            const float* kr = Kb + (size_t)ki * DHEAD;
            d[j] = q0 * kr[lane * 2] + q1 * kr[lane * 2 + 1];
        }
#pragma unroll
        for (int j = 0; j < 8; j++) d[j] = warp_sum(d[j]);
#pragma unroll
        for (int j = 0; j < 8; j++) { mx = fmaxf(mx, d[j]); sm += d[j]; }
    }
    if (lane == 0) Mout[gwarp] = mx - sm / (float)LSEQ;
}

// ---------------- top-40 via bitonic sort of 2048 keys ----------------
#define SORTN 2048
__global__ void __launch_bounds__(256)
topk_kernel(const float* __restrict__ Min, int* __restrict__ Mtop) {
    __shared__ unsigned long long keys[SORTN];
    int bh = blockIdx.x;
    int tid = threadIdx.x;
    for (int j = tid; j < SORTN; j += 256) {
        unsigned long long key;
        if (j < LSEQ) {
            uint32_t b = __float_as_uint(Min[bh * LSEQ + j]);
            uint32_t s = (b & 0x80000000u) ? ~b : (b | 0x80000000u);
            key = ((unsigned long long)(~s) << 32) | (uint32_t)j;
        } else {
            key = 0xFFFFFFFFFFFFFFFFull;
        }
        keys[j] = key;
    }
    __syncthreads();
    for (int k = 2; k <= SORTN; k <<= 1) {
        for (int j = k >> 1; j > 0; j >>= 1) {
#pragma unroll 4
            for (int t = tid; t < SORTN / 2; t += 256) {
                int i = ((t / j) * j * 2) + (t % j);
                int l2 = i + j;
                bool up = ((i & k) == 0);
                unsigned long long a = keys[i], b = keys[l2];
                if ((a > b) == up) { keys[i] = b; keys[l2] = a; }
            }
            __syncthreads();
        }
    }
    if (tid < UTOP)
        Mtop[bh * UTOP + tid] = (int)(keys[tid] & 0xFFFFFFFFull);
}

// ---------------- V mean per (b,h) ----------------
#define VSLICE 377
__global__ void vmean_kernel(const float* __restrict__ V, float* __restrict__ vmean) {
    __shared__ float part[4][DHEAD];
    int bh = blockIdx.x;
    int tid = threadIdx.x;
    int d = tid & 63;
    int sl = tid >> 6;
    const float* Vb = V + (size_t)bh * LSEQ * DHEAD;
    float s = 0.f;
    int beg = sl * VSLICE, end = beg + VSLICE;
    for (int l = beg; l < end; l++) s += Vb[(size_t)l * DHEAD + d];
    part[sl][d] = s;
    __syncthreads();
    if (tid < DHEAD)
        vmean[bh * DHEAD + tid] =
            (part[0][tid] + part[1][tid] + part[2][tid] + part[3][tid]) / (float)LSEQ;
}

// ---------------- attention: tiled multi-query (R14 version) ----------------
#define AQ 8
#define NCHUNK ((LSEQ + 31) / 32)
__global__ void __launch_bounds__(256)
attn_kernel(const float* __restrict__ Q, const float* __restrict__ K,
            const float* __restrict__ V, const int* __restrict__ Mtop,
            float* __restrict__ upd) {
    __shared__ float qs[AQ][DHEAD];
    __shared__ float Ks[32][65];
    __shared__ float2 Vs[32][33];
    __shared__ float ps[AQ][32];
    int bh = blockIdx.x / 5;
    int grp = blockIdx.x % 5;
    int tid = threadIdx.x;
    int w = tid >> 5;
    int lane = tid & 31;
    int u = grp * AQ + w;
    int qi = bh * UTOP + u;

    for (int e = tid; e < AQ * DHEAD; e += 256) {
        int uu = e >> 6, d = e & 63;
        int ll = Mtop[bh * UTOP + grp * AQ + uu];
        qs[uu][d] = Q[((size_t)bh * LSEQ + ll) * DHEAD + d];
    }
    __syncthreads();

    const float* Kb = K + (size_t)bh * LSEQ * DHEAD;
    const float* Vb = V + (size_t)bh * LSEQ * DHEAD;

    float m = NEG_INF, s = 0.f, acc0 = 0.f, acc1 = 0.f;

    for (int c = 0; c < NCHUNK; c++) {
        int base = c * 32;
        int nk = LSEQ - base; if (nk > 32) nk = 32;
        for (int e = tid; e < nk * DHEAD; e += 256) {
            int row = e >> 6, d = e & 63;
            Ks[row][d] = Kb[(size_t)(base + row) * DHEAD + d];
        }
        for (int e = tid; e < nk * 32; e += 256) {
            int row = e >> 5, dp = e & 31;
            Vs[row][dp] = *reinterpret_cast<const float2*>(
                Vb + (size_t)(base + row) * DHEAD + dp * 2);
        }
        __syncthreads();

        bool valid = (lane < nk);
        float dot = 0.f;
#pragma unroll 16
        for (int d = 0; d < DHEAD; d++)
            dot += Ks[lane][d] * qs[w][d];
        dot *= 0.125f;
        if (!valid) dot = NEG_INF;
        float cm = warp_max(dot);
        float nm = fmaxf(m, cm);
        float scale = __expf(m - nm);
        float p = valid ? __expf(dot - nm) : 0.f;
        ps[w][lane] = p;
        float cs = warp_sum(p);
        s = s * scale + cs;
        acc0 *= scale;
        acc1 *= scale;
        m = nm;
        __syncwarp();
#pragma unroll 8
        for (int k = 0; k < 32; k++) {
            float pk = ps[w][k];
            float2 vv = Vs[k][lane];
            acc0 += pk * vv.x;
            acc1 += pk * vv.y;
        }
        __syncthreads();
    }
    float inv = 1.f / s;
    upd[(size_t)qi * DHEAD + lane * 2]     = acc0 * inv;
    upd[(size_t)qi * DHEAD + lane * 2 + 1] = acc1 * inv;
}

// ---------------- sel map ----------------
__global__ void selinit_kernel(int* __restrict__ sel) {
    int idx = blockIdx.x * blockDim.x + threadIdx.x;
    if (idx < BHCNT * LSEQ) sel[idx] = -1;
}
__global__ void selset_kernel(const int* __restrict__ Mtop, int* __restrict__ sel) {
    int idx = blockIdx.x * blockDim.x + threadIdx.x;
    if (idx >= BHCNT * UTOP) return;
    sel[(idx / UTOP) * LSEQ + Mtop[idx]] = idx % UTOP;
}

// ---------------- launch ----------------
extern "C" void kernel_launch(void* const* d_in, const int* in_sizes, int n_in,
                              void* d_out, int out_size) {
    const float* x       = (const float*)d_in[0];
    const float* conv1_w = (const float*)d_in[1];
    const float* conv1_b = (const float*)d_in[2];
    const float* conv2_w = (const float*)d_in[3];
    const float* conv2_b = (const float*)d_in[4];
    const float* wq = (const float*)d_in[5];
    const float* bq = (const float*)d_in[6];
    const float* wk = (const float*)d_in[7];
    const float* bk = (const float*)d_in[8];
    const float* wv = (const float*)d_in[9];
    const float* bv = (const float*)d_in[10];
    const float* wo = (const float*)d_in[11];
    const float* bo = (const float*)d_in[12];
    const int* index_sample = (const int*)d_in[13];
    float* out = (float*)d_out;

    float *xcl, *h1cl, *part, *Qp, *Kp, *Vp, *Mv, *updv, *vmeanv;
    float *B1, *B2, *wqkvT, *woT;
    int *mtop, *sel;
    cudaGetSymbolAddress((void**)&xcl, g_xcl);
    cudaGetSymbolAddress((void**)&h1cl, g_h1cl);
    cudaGetSymbolAddress((void**)&part, g_part);
    cudaGetSymbolAddress((void**)&Qp, g_Q);
    cudaGetSymbolAddress((void**)&Kp, g_K);
    cudaGetSymbolAddress((void**)&Vp, g_V);
    cudaGetSymbolAddress((void**)&Mv, g_M);
    cudaGetSymbolAddress((void**)&mtop, g_Mtop);
    cudaGetSymbolAddress((void**)&updv, g_upd);
    cudaGetSymbolAddress((void**)&vmeanv, g_vmean);
    cudaGetSymbolAddress((void**)&B1, g_B1);
    cudaGetSymbolAddress((void**)&B2, g_B2);
    cudaGetSymbolAddress((void**)&wqkvT, g_wqkvT);
    cudaGetSymbolAddress((void**)&woT, g_woT);
    cudaGetSymbolAddress((void**)&sel, g_sel);

    cudaFuncSetAttribute((const void*)gemm_tc_kernel<1, K1, true, 1, 0, 1>,
                         cudaFuncAttributeMaxDynamicSharedMemorySize, GEMM_SMEM_BYTES);
    cudaFuncSetAttribute((const void*)gemm_tc_kernel<2, K2, false, 1, 0, 2>,
                         cudaFuncAttributeMaxDynamicSharedMemorySize, GEMM_SMEM_BYTES);
    cudaFuncSetAttribute((const void*)gemm_tc_kernel<4, HID, false, 3, 1, 1>,
                         cudaFuncAttributeMaxDynamicSharedMemorySize, GEMM_SMEM_BYTES);
    cudaFuncSetAttribute((const void*)gemm_tc_kernel<3, HID, false, 1, 0, 1>,
                         cudaFuncAttributeMaxDynamicSharedMemorySize, GEMM_SMEM_BYTES);

    // fused prep
    prep_kernel<<<(PREP_S4 + 255) / 256, 256>>>(x, conv1_w, conv2_w, wq, wk, wv, wo,
                                                xcl, B1, B2, wqkvT, woT);

    // conv1 -> h1cl (NHWC row-major), relu
    gemm_tc_kernel<1, K1, true, 1, 0, 1>
        <<<(M1 + 127) / 128, 256, GEMM_SMEM_BYTES>>>(xcl, B1, conv1_b, conv1_b, conv1_b,
                                                     h1cl, h1cl, h1cl, M1,
                                                     nullptr, nullptr, nullptr);

    // conv2 split-K=2 -> raw partials
    gemm_tc_kernel<2, K2, false, 1, 0, 2>
        <<<dim3((M2 + 127) / 128, 1, 2), 256, GEMM_SMEM_BYTES>>>(
            h1cl, B2, conv2_b, conv2_b, conv2_b, part, part, part, M2,
            nullptr, nullptr, nullptr);

    // QKV with fused partial-reduce (+conv2 bias, relu) in the A path
    gemm_tc_kernel<4, HID, false, 3, 1, 1>
        <<<dim3((M2 + 127) / 128, 3), 256, GEMM_SMEM_BYTES>>>(part, wqkvT, bq, bk, bv,
                                                              Qp, Kp, Vp, M2,
                                                              nullptr, nullptr, conv2_b);

    // sampled scores -> M (per-warp, R14 version)
    {
        int warps = BHCNT * LSEQ;
        sampled_m_kernel<<<(warps + 7) / 8, 256>>>(Qp, Kp, index_sample, Mv);
    }

    // top-40 (bitonic) + vmean
    topk_kernel<<<BHCNT, 256>>>(Mv, mtop);
    vmean_kernel<<<BHCNT, 256>>>(Vp, vmeanv);

    // sel map
    selinit_kernel<<<(BHCNT * LSEQ + 255) / 256, 256>>>(sel);
    selset_kernel<<<(BHCNT * UTOP + 255) / 256, 256>>>(mtop, sel);

    // attention (tiled multi-query)
    attn_kernel<<<BHCNT * 5, 256>>>(Qp, Kp, Vp, mtop, updv);

    // final projection with fused ctx gather (MODE 3)
    gemm_tc_kernel<3, HID, false, 1, 0, 1>
        <<<(M2 + 127) / 128, 256, GEMM_SMEM_BYTES>>>(nullptr, woT, bo, bo, bo,
                                                     out, out, out, M2,
                                                     sel, updv, vmeanv);
}

// round 17
// speedup vs baseline: 1.8725x; 1.0015x over previous
#include <cuda_runtime.h>
#include <cstdint>
#include <math.h>

#define NEG_INF (__int_as_float(0xff800000))

// ---------------- problem constants ----------------
#define BATCH   16
#define NFEAT   16
#define TLEN    64
#define SCL     32
#define HID     128
#define FS      4
#define NHEAD   2
#define DHEAD   64

#define H1H     61
#define H1W     29
#define H2H     58
#define H2W     26
#define LSEQ    1508
#define UTOP    40

#define K1      256
#define K2      2048
#define M1      (BATCH*H1H*H1W)   // 28304
#define M2      (BATCH*LSEQ)      // 24128
#define BHCNT   (BATCH*NHEAD)     // 32

#if defined(__CUDA_ARCH_FEAT_SM103_ALL) || defined(__CUDA_ARCH_SPECIFIC__)
#define TC_PATH 1
#else
#define TC_PATH 0
#endif

// ---------------- scratch ----------------
__device__ float g_xcl[BATCH*TLEN*SCL*NFEAT];
__device__ float g_h1cl[M1*HID];
__device__ float g_part[2*M2*HID];
__device__ float g_Q[BHCNT*LSEQ*DHEAD];
__device__ float g_K[BHCNT*LSEQ*DHEAD];
__device__ float g_V[BHCNT*LSEQ*DHEAD];
__device__ float g_M[BHCNT*LSEQ];
__device__ int   g_Mtop[BHCNT*UTOP];
__device__ float g_upd[BHCNT*UTOP*DHEAD];
__device__ float g_vmean[BHCNT*DHEAD];
__device__ float g_B1[HID*K1];
__device__ float g_B2[HID*K2];
__device__ float g_wqkvT[3*HID*HID];
__device__ float g_woT[HID*HID];
__device__ int   g_sel[BHCNT*LSEQ];

// ---------------- PTX helpers ----------------
__device__ __forceinline__ uint32_t smem_u32(const void* p) {
    uint32_t a;
    asm("{ .reg .u64 t; cvta.to.shared.u64 t, %1; cvt.u32.u64 %0, t; }" : "=r"(a) : "l"(p));
    return a;
}

#define TC_ALLOC(sa, n) \
    asm volatile("tcgen05.alloc.cta_group::1.sync.aligned.shared::cta.b32 [%0], %1;" \
                 :: "r"(sa), "r"(n) : "memory")
#define TC_DEALLOC(t, n) \
    asm volatile("tcgen05.dealloc.cta_group::1.sync.aligned.b32 %0, %1;" :: "r"(t), "r"(n))
#define TC_RELINQ() \
    asm volatile("tcgen05.relinquish_alloc_permit.cta_group::1.sync.aligned;")
#define TC_COMMIT(mb) \
    asm volatile("tcgen05.commit.cta_group::1.mbarrier::arrive::one.shared::cluster.b64 [%0];" \
                 :: "r"(mb) : "memory")
#define TC_FENCE_AFTER()  asm volatile("tcgen05.fence::after_thread_sync;" ::: "memory")
#define TC_FENCE_BEFORE() asm volatile("tcgen05.fence::before_thread_sync;" ::: "memory")
#define TC_WAIT_LD()      asm volatile("tcgen05.wait::ld.sync.aligned;" ::: "memory")
#define MB_INIT(mb, c) \
    asm volatile("mbarrier.init.shared.b64 [%0], %1;" :: "r"(mb), "r"(c) : "memory")
#define FENCE_ASYNC() asm volatile("fence.proxy.async.shared::cta;" ::: "memory")

#define MB_WAIT_PARITY(mbar_smem_addr, phase_parity) do { \
    uint32_t _mbar = (uint32_t)(mbar_smem_addr); \
    uint32_t _parity = (uint32_t)(phase_parity); \
    uint32_t _done; \
    asm volatile( \
        "{\n\t" \
        ".reg .pred p;\n\t" \
        "mbarrier.try_wait.parity.acquire.cta.shared::cta.b64 p, [%1], %2;\n\t" \
        "selp.b32 %0, 1, 0, p;\n\t" \
        "}" \
        : "=r"(_done) : "r"(_mbar), "r"(_parity) : "memory"); \
    if (!_done) { \
        asm volatile( \
            "{\n\t" \
            ".reg .pred P1;\n\t" \
            "WAIT_LOOP_%=:\n\t" \
            "mbarrier.try_wait.parity.acquire.cta.shared::cta.b64 P1, [%0], %1, 0x989680;\n\t" \
            "@P1 bra.uni WAIT_DONE_%=;\n\t" \
            "bra.uni WAIT_LOOP_%=;\n\t" \
            "WAIT_DONE_%=:\n\t" \
            "}" \
            :: "r"(_mbar), "r"(_parity) : "memory"); \
    } \
} while(0)

#define TC_LD_X32(r, tmem_addr) \
    asm volatile( \
        "tcgen05.ld.sync.aligned.32x32b.x32.b32 " \
        "{%0, %1, %2, %3, %4, %5, %6, %7, " \
        " %8, %9, %10, %11, %12, %13, %14, %15, " \
        " %16, %17, %18, %19, %20, %21, %22, %23, " \
        " %24, %25, %26, %27, %28, %29, %30, %31}, [%32];" \
        : "=r"((r)[0]),  "=r"((r)[1]),  "=r"((r)[2]),  "=r"((r)[3]), \
          "=r"((r)[4]),  "=r"((r)[5]),  "=r"((r)[6]),  "=r"((r)[7]), \
          "=r"((r)[8]),  "=r"((r)[9]),  "=r"((r)[10]), "=r"((r)[11]), \
          "=r"((r)[12]), "=r"((r)[13]), "=r"((r)[14]), "=r"((r)[15]), \
          "=r"((r)[16]), "=r"((r)[17]), "=r"((r)[18]), "=r"((r)[19]), \
          "=r"((r)[20]), "=r"((r)[21]), "=r"((r)[22]), "=r"((r)[23]), \
          "=r"((r)[24]), "=r"((r)[25]), "=r"((r)[26]), "=r"((r)[27]), \
          "=r"((r)[28]), "=r"((r)[29]), "=r"((r)[30]), "=r"((r)[31]) \
        : "r"(tmem_addr))

#if TC_PATH
__device__ __forceinline__ void mma_tf32_ss(uint32_t d_tmem, uint64_t a_desc,
                                            uint64_t b_desc, uint32_t idesc, bool accum) {
    uint32_t en = accum ? 1u : 0u;
    asm volatile(
        "{\n\t"
        ".reg .pred p;\n\t"
        "setp.ne.u32 p, %4, 0;\n\t"
        "tcgen05.mma.cta_group::1.kind::tf32 [%0], %1, %2, %3, p;\n\t"
        "}"
        :: "r"(d_tmem), "l"(a_desc), "l"(b_desc), "r"(idesc), "r"(en)
        : "memory");
}
#endif

__device__ __forceinline__ uint64_t make_desc(uint32_t addr) {
    return ((uint64_t)2 << 61) | ((uint64_t)1 << 46) | ((uint64_t)64 << 32)
         | ((uint64_t)1 << 16) | (uint64_t)((addr >> 4) & 0x3FFF);
}

__device__ __forceinline__ uint32_t swz128(uint32_t off) {
    return off ^ ((off >> 3) & 0x70);
}

__device__ __forceinline__ void split_tf32(float v, float& hi, float& lo) {
    uint32_t h;
    asm("cvt.rna.tf32.f32 %0, %1;" : "=r"(h) : "f"(v));
    hi = __uint_as_float(h);
    lo = v - hi;
}

#define TF32_IDESC ((1u << 4) | (2u << 7) | (2u << 10) | (16u << 17) | (8u << 24))

// ---------------- fused prep kernel ----------------
#define PREP_S0 (BATCH*NFEAT*TLEN*SCL)
#define PREP_S1 (PREP_S0 + HID*K1)
#define PREP_S2 (PREP_S1 + HID*K2)
#define PREP_S3 (PREP_S2 + 3*HID*HID)
#define PREP_S4 (PREP_S3 + HID*HID)
__global__ void prep_kernel(const float* __restrict__ x,
                            const float* __restrict__ c1w, const float* __restrict__ c2w,
                            const float* __restrict__ wq, const float* __restrict__ wk,
                            const float* __restrict__ wv, const float* __restrict__ wo,
                            float* __restrict__ xcl, float* __restrict__ B1,
                            float* __restrict__ B2, float* __restrict__ wqkvT,
                            float* __restrict__ woT) {
    int idx = blockIdx.x * blockDim.x + threadIdx.x;
    if (idx < PREP_S0) {
        int w = idx % SCL;
        int h = (idx / SCL) % TLEN;
        int c = (idx / (SCL * TLEN)) % NFEAT;
        int b = idx / (SCL * TLEN * NFEAT);
        xcl[((b * TLEN + h) * SCL + w) * NFEAT + c] = x[idx];
    } else if (idx < PREP_S1) {
        int i = idx - PREP_S0;
        int n = i / K1, k = i % K1;
        int ic = k / 16, s = k % 16;
        B1[n * K1 + s * NFEAT + ic] = c1w[i];
    } else if (idx < PREP_S2) {
        int i = idx - PREP_S1;
        int n = i / K2, k = i % K2;
        int ic = k / 16, s = k % 16;
        B2[n * K2 + s * HID + ic] = c2w[i];
    } else if (idx < PREP_S3) {
        int i = idx - PREP_S2;
        int mat = i / (HID * HID);
        int r = i % (HID * HID);
        int a = r / HID, b = r % HID;
        const float* w = (mat == 0) ? wq : (mat == 1) ? wk : wv;
        wqkvT[mat * HID * HID + b * HID + a] = w[r];
    } else if (idx < PREP_S4) {
        int i = idx - PREP_S3;
        int a = i / HID, b = i % HID;
        woT[b * HID + a] = wo[i];
    }
}

// ---------------- tcgen05 3xTF32 GEMM ----------------
// MODE 0: A row-major. MODE 1: conv1 im2col. MODE 2: conv2 im2col.
// MODE 3: A gathered from (upd|vmean) via sel. MODE 4: A = relu(part0+part1+biasA).
// SPLITK > 1: grid.z splits K; raw partial written to o0 + z*M*HID.
#define GEMM_SMEM_BYTES (79872)

template<int MODE, int KDIM, bool RELU, int NMAT, int LAYOUT, int SPLITK>
__global__ void __launch_bounds__(256, 2)
gemm_tc_kernel(const float* __restrict__ Ain, const float* __restrict__ BwAll,
               const float* __restrict__ b0, const float* __restrict__ b1p,
               const float* __restrict__ b2p,
               float* __restrict__ o0, float* __restrict__ o1p, float* __restrict__ o2p,
               int M,
               const int* __restrict__ sel, const float* __restrict__ updp,
               const float* __restrict__ vmeanp) {
    const int mat = (NMAT > 1) ? blockIdx.y : 0;
    const float* Bw = BwAll + (size_t)mat * HID * KDIM;
    const float* bias = (mat == 0) ? b0 : (mat == 1) ? b1p : b2p;
    float* out = (mat == 0) ? o0 : (mat == 1) ? o1p : o2p;
    const int kbeg = (SPLITK > 1) ? blockIdx.z * (KDIM / SPLITK) : 0;

#if TC_PATH
    extern __shared__ char dynraw[];
    __shared__ uint32_t s_tmem[1];
    __shared__ __align__(8) unsigned long long s_mbar[1];

    const int tid = threadIdx.x;
    const int wid = tid >> 5;
    const int lane = tid & 31;
    const int block_m = blockIdx.x * 128;

    uint32_t dynb32 = smem_u32(dynraw);
    uint32_t smem_base = (dynb32 + 1023u) & ~1023u;
    char* dbase = dynraw + (smem_base - dynb32);
    uint32_t mbar0 = smem_u32(&s_mbar[0]);

    if (wid == 0) {
        TC_ALLOC(smem_u32(s_tmem), 256);
        TC_RELINQ();
    }
    if (tid == 0) MB_INIT(mbar0, 1);
    __syncthreads();
    uint32_t tmem;
    asm volatile("ld.shared.b32 %0, [%1];" : "=r"(tmem) : "r"(smem_u32(s_tmem)));

    const int quad = tid & 7;
    int rowi[4], abase[4], bh2[4];
    bool aok[4];
#pragma unroll
    for (int i = 0; i < 4; i++) {
        rowi[i] = i * 32 + (tid >> 3);
        int m = block_m + rowi[i];
        aok[i] = (m < M);
        int mc = aok[i] ? m : 0;
        bh2[i] = 0;
        if (MODE == 0 || MODE == 4) {
            abase[i] = mc * KDIM;
        } else if (MODE == 1) {
            int b = mc / (H1H * H1W);
            int r = mc % (H1H * H1W);
            abase[i] = ((b * TLEN + r / H1W) * SCL + (r % H1W)) * NFEAT;
        } else if (MODE == 2) {
            int b = mc / LSEQ;
            int r = mc % LSEQ;
            abase[i] = ((b * H1H + r / H2W) * H1W + (r % H2W)) * HID;
        } else {
            int b = mc / LSEQ;
            int l = mc % LSEQ;
            abase[i] = b * NHEAD * LSEQ + l;
            bh2[i] = b * NHEAD;
        }
    }
    uint32_t swz[4];
#pragma unroll
    for (int i = 0; i < 4; i++)
        swz[i] = swz128((uint32_t)rowi[i] * 128u + (uint32_t)quad * 16u);

    float4 areg[4], breg[4];
    auto load_regs = [&](int c) {
        const int kq = kbeg + c * 32 + quad * 4;
#pragma unroll
        for (int i = 0; i < 4; i++) {
            areg[i] = make_float4(0.f, 0.f, 0.f, 0.f);
            if (aok[i]) {
                if (MODE == 3) {
                    int h = kq >> 6, d = kq & 63;
                    int u = __ldg(&sel[abase[i] + h * LSEQ]);
                    int bh = bh2[i] + h;
                    const float* src = (u >= 0)
                        ? updp + ((size_t)bh * UTOP + u) * DHEAD + d
                        : vmeanp + bh * DHEAD + d;
                    areg[i] = *reinterpret_cast<const float4*>(src);
                } else if (MODE == 4) {
                    int addr = abase[i] + kq;
                    float4 p0 = *reinterpret_cast<const float4*>(Ain + addr);
                    float4 p1 = *reinterpret_cast<const float4*>(Ain + (size_t)M2 * HID + addr);
                    float4 bb = *reinterpret_cast<const float4*>(vmeanp + kq);
                    areg[i].x = fmaxf(p0.x + p1.x + bb.x, 0.f);
                    areg[i].y = fmaxf(p0.y + p1.y + bb.y, 0.f);
                    areg[i].z = fmaxf(p0.z + p1.z + bb.z, 0.f);
                    areg[i].w = fmaxf(p0.w + p1.w + bb.w, 0.f);
                } else {
                    int addr;
                    if (MODE == 0) {
                        addr = abase[i] + kq;
                    } else if (MODE == 1) {
                        int s = kq >> 4, ic = kq & 15;
                        addr = abase[i] + (((s >> 2) * SCL) + (s & 3)) * NFEAT + ic;
                    } else {
                        int s = kq >> 7, ic = kq & 127;
                        addr = abase[i] + (((s >> 2) * H1W) + (s & 3)) * HID + ic;
                    }
                    areg[i] = *reinterpret_cast<const float4*>(Ain + addr);
                }
            }
            breg[i] = *reinterpret_cast<const float4*>(Bw + rowi[i] * KDIM + kq);
        }
    };
    auto store_tiles = [&]() {
        char* Ahi = dbase;
        char* Alo = Ahi + 16384;
        char* Bhi = Ahi + 32768;
        char* Blo = Ahi + 49152;
#pragma unroll
        for (int i = 0; i < 4; i++) {
            float4 h4, l4;
            split_tf32(areg[i].x, h4.x, l4.x);
            split_tf32(areg[i].y, h4.y, l4.y);
            split_tf32(areg[i].z, h4.z, l4.z);
            split_tf32(areg[i].w, h4.w, l4.w);
            *reinterpret_cast<float4*>(Ahi + swz[i]) = h4;
            *reinterpret_cast<float4*>(Alo + swz[i]) = l4;
            split_tf32(breg[i].x, h4.x, l4.x);
            split_tf32(breg[i].y, h4.y, l4.y);
            split_tf32(breg[i].z, h4.z, l4.z);
            split_tf32(breg[i].w, h4.w, l4.w);
            *reinterpret_cast<float4*>(Bhi + swz[i]) = h4;
            *reinterpret_cast<float4*>(Blo + swz[i]) = l4;
        }
    };

    const int NC = (KDIM / SPLITK) / 32;
    int ph = 0;
    load_regs(0);

    for (int c = 0; c < NC; c++) {
        if (c > 0) {
            MB_WAIT_PARITY(mbar0, ph);
            ph ^= 1;
        }
        store_tiles();
        if (c + 1 < NC) load_regs(c + 1);
        FENCE_ASYNC();
        __syncthreads();
        if (tid == 0) {
            uint64_t dah = make_desc(smem_base);
            uint64_t dal = make_desc(smem_base + 16384);
            uint64_t dbh = make_desc(smem_base + 32768);
            uint64_t dbl = make_desc(smem_base + 49152);
#pragma unroll
            for (int s = 0; s < 4; s++) {
                uint64_t o = (uint64_t)(s * 2);
                mma_tf32_ss(tmem, dah + o, dbh + o, TF32_IDESC, !(c == 0 && s == 0));
                mma_tf32_ss(tmem, dah + o, dbl + o, TF32_IDESC, true);
                mma_tf32_ss(tmem, dal + o, dbh + o, TF32_IDESC, true);
            }
            TC_COMMIT(mbar0);
        }
    }
    MB_WAIT_PARITY(mbar0, ph);
    TC_FENCE_AFTER();
    __syncthreads();

    if (wid < 4) {
        int m = block_m + wid * 32 + lane;
#pragma unroll
        for (int cb = 0; cb < 128; cb += 32) {
            uint32_t r[32];
            TC_LD_X32(r, tmem + cb);
            TC_WAIT_LD();
            if (m < M) {
                float vals[32];
#pragma unroll
                for (int j = 0; j < 32; j++) {
                    float v = __uint_as_float(r[j]);
                    if (SPLITK == 1) {
                        v += __ldg(&bias[cb + j]);
                        if (RELU) v = fmaxf(v, 0.f);
                    }
                    vals[j] = v;
                }
                float* po;
                if (SPLITK > 1) {
                    po = o0 + ((size_t)blockIdx.z * M + m) * HID + cb;
                } else if (LAYOUT == 0) {
                    po = out + (size_t)m * HID + cb;
                } else {
                    int b = m / LSEQ, l = m % LSEQ;
                    int h = cb >> 6, d0 = cb & 63;
                    po = out + ((size_t)(b * NHEAD + h) * LSEQ + l) * DHEAD + d0;
                }
#pragma unroll
                for (int j = 0; j < 8; j++) {
                    *reinterpret_cast<float4*>(po + j * 4) =
                        make_float4(vals[j * 4], vals[j * 4 + 1], vals[j * 4 + 2], vals[j * 4 + 3]);
                }
            }
        }
        TC_FENCE_BEFORE();
    }
    __syncthreads();
    if (wid == 0) TC_DEALLOC(tmem, 256);
#else
    // naive fallback (family PTX pass; exact sm_103a cubin preferred on GB300)
    const int tid = threadIdx.x;
    const int block_m = blockIdx.x * 128;
    const int kdiv = KDIM / SPLITK;
    for (int e = tid; e < 128 * 128; e += 256) {
        int mi = e >> 7, n = e & 127;
        int m = block_m + mi;
        if (m >= M) continue;
        float acc = 0.f;
        for (int kk = 0; kk < kdiv; kk++) {
            int k = kbeg + kk;
            float a;
            if (MODE == 0) {
                a = Ain[(size_t)m * KDIM + k];
            } else if (MODE == 1) {
                int b = m / (H1H * H1W), r = m % (H1H * H1W);
                int s = k >> 4, ic = k & 15;
                a = Ain[((b * TLEN + r / H1W + (s >> 2)) * SCL + (r % H1W) + (s & 3)) * NFEAT + ic];
            } else if (MODE == 2) {
                int b = m / LSEQ, r = m % LSEQ;
                int s = k >> 7, ic = k & 127;
                a = Ain[((b * H1H + r / H2W + (s >> 2)) * H1W + (r % H2W) + (s & 3)) * HID + ic];
            } else if (MODE == 4) {
                int addr = m * KDIM + k;
                a = fmaxf(Ain[addr] + Ain[(size_t)M2 * HID + addr] + vmeanp[k], 0.f);
            } else {
                int b = m / LSEQ, l = m % LSEQ;
                int h = k >> 6, d = k & 63;
                int u = sel[(b * NHEAD + h) * LSEQ + l];
                int bh = b * NHEAD + h;
                a = (u >= 0) ? updp[((size_t)bh * UTOP + u) * DHEAD + d]
                             : vmeanp[bh * DHEAD + d];
            }
            acc += a * Bw[n * KDIM + k];
        }
        if (SPLITK > 1) {
            o0[((size_t)blockIdx.z * M + m) * HID + n] = acc;
        } else {
            acc += bias[n];
            if (RELU) acc = fmaxf(acc, 0.f);
            if (LAYOUT == 0) {
                out[(size_t)m * HID + n] = acc;
            } else {
                int b = m / LSEQ, l = m % LSEQ;
                int h = n >> 6, d = n & 63;
                out[((size_t)(b * NHEAD + h) * LSEQ + l) * DHEAD + d] = acc;
            }
        }
    }
#endif
}

// ---------------- helpers ----------------
__device__ __forceinline__ float warp_sum(float v) {
    v += __shfl_xor_sync(0xffffffffu, v, 16);
    v += __shfl_xor_sync(0xffffffffu, v, 8);
    v += __shfl_xor_sync(0xffffffffu, v, 4);
    v += __shfl_xor_sync(0xffffffffu, v, 2);
    v += __shfl_xor_sync(0xffffffffu, v, 1);
    return v;
}
__device__ __forceinline__ float warp_max(float v) {
    v = fmaxf(v, __shfl_xor_sync(0xffffffffu, v, 16));
    v = fmaxf(v, __shfl_xor_sync(0xffffffffu, v, 8));
    v = fmaxf(v, __shfl_xor_sync(0xffffffffu, v, 4));
    v = fmaxf(v, __shfl_xor_sync(0xffffffffu, v, 2));
    v = fmaxf(v, __shfl_xor_sync(0xffffffffu, v, 1));
    return v;
}

// ---------------- sampled scores -> M (per-warp) ----------------
__global__ void sampled_m_kernel(const float* __restrict__ Q, const float* __restrict__ K,
                                 const int* __restrict__ idxs, float* __restrict__ Mout) {
    int gwarp = (blockIdx.x * blockDim.x + threadIdx.x) >> 5;
    int lane = threadIdx.x & 31;
    if (gwarp >= BHCNT * LSEQ) return;
    int bh = gwarp / LSEQ;
    int l  = gwarp % LSEQ;
    const float* q = Q + (size_t)gwarp * DHEAD;
    float q0 = q[lane * 2], q1 = q[lane * 2 + 1];
    const float* Kb = K + (size_t)bh * LSEQ * DHEAD;
    float mx = NEG_INF, sm = 0.f;
#pragma unroll 1
    for (int u = 0; u < UTOP; u += 8) {
        float d[8];
#pragma unroll
        for (int j = 0; j < 8; j++) {
            int ki = __ldg(&idxs[l * UTOP + u + j]);
            const float* kr = Kb + (size_t)ki * DHEAD;
            d[j] = q0 * kr[lane * 2] + q1 * kr[lane * 2 + 1];
        }
#pragma unroll
        for (int j = 0; j < 8; j++) d[j] = warp_sum(d[j]);
#pragma unroll
        for (int j = 0; j < 8; j++) { mx = fmaxf(mx, d[j]); sm += d[j]; }
    }
    if (lane == 0) Mout[gwarp] = mx - sm / (float)LSEQ;
}

// ---------------- top-40 (bitonic) + fused sel-map build ----------------
#define SORTN 2048
__global__ void __launch_bounds__(256)
topk_kernel(const float* __restrict__ Min, int* __restrict__ Mtop, int* __restrict__ sel) {
    __shared__ unsigned long long keys[SORTN];
    int bh = blockIdx.x;
    int tid = threadIdx.x;
    // init this bh's sel row while loading sort keys
    for (int j = tid; j < LSEQ; j += 256) sel[bh * LSEQ + j] = -1;
    for (int j = tid; j < SORTN; j += 256) {
        unsigned long long key;
        if (j < LSEQ) {
            uint32_t b = __float_as_uint(Min[bh * LSEQ + j]);
            uint32_t s = (b & 0x80000000u) ? ~b : (b | 0x80000000u);
            key = ((unsigned long long)(~s) << 32) | (uint32_t)j;
        } else {
            key = 0xFFFFFFFFFFFFFFFFull;
        }
        keys[j] = key;
    }
    __syncthreads();
    for (int k = 2; k <= SORTN; k <<= 1) {
        for (int j = k >> 1; j > 0; j >>= 1) {
#pragma unroll 4
            for (int t = tid; t < SORTN / 2; t += 256) {
                int i = ((t / j) * j * 2) + (t % j);
                int l2 = i + j;
                bool up = ((i & k) == 0);
                unsigned long long a = keys[i], b = keys[l2];
                if ((a > b) == up) { keys[i] = b; keys[l2] = a; }
            }
            __syncthreads();
        }
    }
    if (tid < UTOP) {
        int l = (int)(keys[tid] & 0xFFFFFFFFull);
        Mtop[bh * UTOP + tid] = l;
        sel[bh * LSEQ + l] = tid;
    }
}

// ---------------- attention: tiled multi-query + fused vmean ----------------
#define AQ 8
#define NCHUNK ((LSEQ + 31) / 32)
__global__ void __launch_bounds__(256)
attn_kernel(const float* __restrict__ Q, const float* __restrict__ K,
            const float* __restrict__ V, const int* __restrict__ Mtop,
            float* __restrict__ upd, float* __restrict__ vmean) {
    __shared__ float qs[AQ][DHEAD];
    __shared__ float Ks[32][65];
    __shared__ float2 Vs[32][33];
    __shared__ float ps[AQ][32];
    int bh = blockIdx.x / 5;
    int grp = blockIdx.x % 5;
    int tid = threadIdx.x;
    int w = tid >> 5;
    int lane = tid & 31;
    int u = grp * AQ + w;
    int qi = bh * UTOP + u;

    for (int e = tid; e < AQ * DHEAD; e += 256) {
        int uu = e >> 6, d = e & 63;
        int ll = Mtop[bh * UTOP + grp * AQ + uu];
        qs[uu][d] = Q[((size_t)bh * LSEQ + ll) * DHEAD + d];
    }
    __syncthreads();

    const float* Kb = K + (size_t)bh * LSEQ * DHEAD;
    const float* Vb = V + (size_t)bh * LSEQ * DHEAD;

    float m = NEG_INF, s = 0.f, acc0 = 0.f, acc1 = 0.f;
    float vs0 = 0.f, vs1 = 0.f;   // vmean accumulator (warp 0 of grp 0)
    const bool do_vmean = (grp == 0 && w == 0);

    for (int c = 0; c < NCHUNK; c++) {
        int base = c * 32;
        int nk = LSEQ - base; if (nk > 32) nk = 32;
        for (int e = tid; e < nk * DHEAD; e += 256) {
            int row = e >> 6, d = e & 63;
            Ks[row][d] = Kb[(size_t)(base + row) * DHEAD + d];
        }
        for (int e = tid; e < nk * 32; e += 256) {
            int row = e >> 5, dp = e & 31;
            Vs[row][dp] = *reinterpret_cast<const float2*>(
                Vb + (size_t)(base + row) * DHEAD + dp * 2);
        }
        __syncthreads();

        bool valid = (lane < nk);
        float dot = 0.f;
#pragma unroll 16
        for (int d = 0; d < DHEAD; d++)
            dot += Ks[lane][d] * qs[w][d];
        dot *= 0.125f;
        if (!valid) dot = NEG_INF;
        float cm = warp_max(dot);
        float nm = fmaxf(m, cm);
        float scale = __expf(m - nm);
        float p = valid ? __expf(dot - nm) : 0.f;
        ps[w][lane] = p;
        float cs = warp_sum(p);
        s = s * scale + cs;
        acc0 *= scale;
        acc1 *= scale;
        m = nm;
        __syncwarp();
#pragma unroll 8
        for (int k = 0; k < 32; k++) {
            float pk = ps[w][k];
            float2 vv = Vs[k][lane];
            acc0 += pk * vv.x;
            acc1 += pk * vv.y;
        }
        if (do_vmean) {
            for (int k = 0; k < nk; k++) {
                float2 vv = Vs[k][lane];
                vs0 += vv.x;
                vs1 += vv.y;
            }
        }
        __syncthreads();
    }
    float inv = 1.f / s;
    upd[(size_t)qi * DHEAD + lane * 2]     = acc0 * inv;
    upd[(size_t)qi * DHEAD + lane * 2 + 1] = acc1 * inv;
    if (do_vmean) {
        vmean[bh * DHEAD + lane * 2]     = vs0 / (float)LSEQ;
        vmean[bh * DHEAD + lane * 2 + 1] = vs1 / (float)LSEQ;
    }
}

// ---------------- launch ----------------
extern "C" void kernel_launch(void* const* d_in, const int* in_sizes, int n_in,
                              void* d_out, int out_size) {
    const float* x       = (const float*)d_in[0];
    const float* conv1_w = (const float*)d_in[1];
    const float* conv1_b = (const float*)d_in[2];
    const float* conv2_w = (const float*)d_in[3];
    const float* conv2_b = (const float*)d_in[4];
    const float* wq = (const float*)d_in[5];
    const float* bq = (const float*)d_in[6];
    const float* wk = (const float*)d_in[7];
    const float* bk = (const float*)d_in[8];
    const float* wv = (const float*)d_in[9];
    const float* bv = (const float*)d_in[10];
    const float* wo = (const float*)d_in[11];
    const float* bo = (const float*)d_in[12];
    const int* index_sample = (const int*)d_in[13];
    float* out = (float*)d_out;

    float *xcl, *h1cl, *part, *Qp, *Kp, *Vp, *Mv, *updv, *vmeanv;
    float *B1, *B2, *wqkvT, *woT;
    int *mtop, *sel;
    cudaGetSymbolAddress((void**)&xcl, g_xcl);
    cudaGetSymbolAddress((void**)&h1cl, g_h1cl);
    cudaGetSymbolAddress((void**)&part, g_part);
    cudaGetSymbolAddress((void**)&Qp, g_Q);
    cudaGetSymbolAddress((void**)&Kp, g_K);
    cudaGetSymbolAddress((void**)&Vp, g_V);
    cudaGetSymbolAddress((void**)&Mv, g_M);
    cudaGetSymbolAddress((void**)&mtop, g_Mtop);
    cudaGetSymbolAddress((void**)&updv, g_upd);
    cudaGetSymbolAddress((void**)&vmeanv, g_vmean);
    cudaGetSymbolAddress((void**)&B1, g_B1);
    cudaGetSymbolAddress((void**)&B2, g_B2);
    cudaGetSymbolAddress((void**)&wqkvT, g_wqkvT);
    cudaGetSymbolAddress((void**)&woT, g_woT);
    cudaGetSymbolAddress((void**)&sel, g_sel);

    cudaFuncSetAttribute((const void*)gemm_tc_kernel<1, K1, true, 1, 0, 1>,
                         cudaFuncAttributeMaxDynamicSharedMemorySize, GEMM_SMEM_BYTES);
    cudaFuncSetAttribute((const void*)gemm_tc_kernel<2, K2, false, 1, 0, 2>,
                         cudaFuncAttributeMaxDynamicSharedMemorySize, GEMM_SMEM_BYTES);
    cudaFuncSetAttribute((const void*)gemm_tc_kernel<4, HID, false, 3, 1, 1>,
                         cudaFuncAttributeMaxDynamicSharedMemorySize, GEMM_SMEM_BYTES);
    cudaFuncSetAttribute((const void*)gemm_tc_kernel<3, HID, false, 1, 0, 1>,
                         cudaFuncAttributeMaxDynamicSharedMemorySize, GEMM_SMEM_BYTES);

    // fused prep
    prep_kernel<<<(PREP_S4 + 255) / 256, 256>>>(x, conv1_w, conv2_w, wq, wk, wv, wo,
                                                xcl, B1, B2, wqkvT, woT);

    // conv1 -> h1cl (NHWC row-major), relu
    gemm_tc_kernel<1, K1, true, 1, 0, 1>
        <<<(M1 + 127) / 128, 256, GEMM_SMEM_BYTES>>>(xcl, B1, conv1_b, conv1_b, conv1_b,
                                                     h1cl, h1cl, h1cl, M1,
                                                     nullptr, nullptr, nullptr);

    // conv2 split-K=2 -> raw partials
    gemm_tc_kernel<2, K2, false, 1, 0, 2>
        <<<dim3((M2 + 127) / 128, 1, 2), 256, GEMM_SMEM_BYTES>>>(
            h1cl, B2, conv2_b, conv2_b, conv2_b, part, part, part, M2,
            nullptr, nullptr, nullptr);

    // QKV with fused partial-reduce (+conv2 bias, relu) in the A path
    gemm_tc_kernel<4, HID, false, 3, 1, 1>
        <<<dim3((M2 + 127) / 128, 3), 256, GEMM_SMEM_BYTES>>>(part, wqkvT, bq, bk, bv,
                                                              Qp, Kp, Vp, M2,
                                                              nullptr, nullptr, conv2_b);

    // sampled scores -> M (per-warp)
    {
        int warps = BHCNT * LSEQ;
        sampled_m_kernel<<<(warps + 7) / 8, 256>>>(Qp, Kp, index_sample, Mv);
    }

    // top-40 (bitonic) + fused sel-map
    topk_kernel<<<BHCNT, 256>>>(Mv, mtop, sel);

    // attention (tiled multi-query) + fused vmean
    attn_kernel<<<BHCNT * 5, 256>>>(Qp, Kp, Vp, mtop, updv, vmeanv);

    // final projection with fused ctx gather (MODE 3)
    gemm_tc_kernel<3, HID, false, 1, 0, 1>
        <<<(M2 + 127) / 128, 256, GEMM_SMEM_BYTES>>>(nullptr, woT, bo, bo, bo,
                                                     out, out, out, M2,
                                                     sel, updv, vmeanv);
}